// round 1
// baseline (speedup 1.0000x reference)
#include <cuda_runtime.h>
#include <math_constants.h>

#define CDIM 256
#define NTOK 4096
#define BM 64
#define BN 64

// Scratch for Q1,K1,V1,Q2,K2,V2: [p][b][d][n], p in {0:q1,1:k1,2:v1,3:q2,4:k2,5:v2}
__device__ float g_qkv[6ull * 4 * CDIM * NTOK];

// ---------------------------------------------------------------------------
// Projection: out[p][b][d][n] = bias[d] + sum_c W[d][c] * x_s[b][c][n]
// grid: (N/64, C/64, 24=p*4+b), 256 threads, 64x64 tile, BK=16
// ---------------------------------------------------------------------------
__global__ __launch_bounds__(256) void proj_kernel(
    const float* __restrict__ x1, const float* __restrict__ x2,
    const float* __restrict__ Wq, const float* __restrict__ bq,
    const float* __restrict__ Wk, const float* __restrict__ bk,
    const float* __restrict__ Wv, const float* __restrict__ bv)
{
    __shared__ float Ws[16][64];   // Ws[c][d]
    __shared__ float Xs[16][64];   // Xs[c][n]

    const int nt = blockIdx.x;
    const int dt = blockIdx.y;
    const int z  = blockIdx.z;
    const int p = z >> 2, b = z & 3;
    const int s = p / 3, w = p % 3;

    const float* X    = (s == 0 ? x1 : x2) + (size_t)b * CDIM * NTOK;
    const float* W    = (w == 0 ? Wq : (w == 1 ? Wk : Wv));
    const float* bias = (w == 0 ? bq : (w == 1 ? bk : bv));
    float* out = g_qkv + ((size_t)p * 4 + b) * CDIM * NTOK;

    const int t  = threadIdx.x;
    const int tx = t & 15, ty = t >> 4;
    const int n0 = nt * 64, d0 = dt * 64;

    float acc[4][4] = {};

    for (int kk = 0; kk < CDIM; kk += 16) {
        // W tile: rows d (64), cols c (16) -> transposed into Ws[c][d]
        {
            const int dd = t >> 2, cc = (t & 3) * 4;
            float4 v = *(const float4*)(W + (size_t)(d0 + dd) * CDIM + kk + cc);
            Ws[cc + 0][dd] = v.x; Ws[cc + 1][dd] = v.y;
            Ws[cc + 2][dd] = v.z; Ws[cc + 3][dd] = v.w;
        }
        // X tile: Xs[c][n]
        {
            const int cc = t >> 4, nn = (t & 15) * 4;
            *(float4*)&Xs[cc][nn] =
                *(const float4*)(X + (size_t)(kk + cc) * NTOK + n0 + nn);
        }
        __syncthreads();

        #pragma unroll
        for (int c = 0; c < 16; ++c) {
            const float4 wv = *(const float4*)&Ws[c][ty * 4];
            const float4 xv = *(const float4*)&Xs[c][tx * 4];
            const float wr[4] = {wv.x, wv.y, wv.z, wv.w};
            const float xr[4] = {xv.x, xv.y, xv.z, xv.w};
            #pragma unroll
            for (int i = 0; i < 4; ++i)
                #pragma unroll
                for (int j = 0; j < 4; ++j)
                    acc[i][j] += wr[i] * xr[j];
        }
        __syncthreads();
    }

    #pragma unroll
    for (int i = 0; i < 4; ++i) {
        const float bb = bias[d0 + ty * 4 + i];
        float4 r;
        r.x = acc[i][0] + bb; r.y = acc[i][1] + bb;
        r.z = acc[i][2] + bb; r.w = acc[i][3] + bb;
        *(float4*)&out[(size_t)(d0 + ty * 4 + i) * NTOK + n0 + tx * 4] = r;
    }
}

// ---------------------------------------------------------------------------
// Flash attention, fp32.
// grid: (N/64, 8=s*4+b), 256 threads. One CTA = 64 query rows, full D=256.
// smem: Qs[256][64], Ks[256][64], Vs[256][65], Ps[64][64]  -> 214016 B
// ---------------------------------------------------------------------------
#define SM_Q 0
#define SM_K (256 * 64)
#define SM_V (2 * 256 * 64)
#define SM_P (2 * 256 * 64 + 256 * 65)
#define SMEM_FLOATS (2 * 256 * 64 + 256 * 65 + 64 * 64)
#define SMEM_BYTES (SMEM_FLOATS * 4)

__global__ __launch_bounds__(256) void attn_kernel(float* __restrict__ out)
{
    extern __shared__ float smem[];
    float* Qs = smem + SM_Q;   // [d][n]  row=64
    float* Ks = smem + SM_K;   // [d][m]  row=64
    float* Vs = smem + SM_V;   // [d][m]  row=65 (pad: scalar access pattern)
    float* Ps = smem + SM_P;   // [n][m]  row=64

    const int nt = blockIdx.x;
    const int z  = blockIdx.y;
    const int s = z >> 2, b = z & 3;

    // stream 0: q=q1(p0), k=k2(p4), v=v1(p2); stream 1: q=q2(p3), k=k1(p1), v=v2(p5)
    const float* Q = g_qkv + ((size_t)(s == 0 ? 0 : 3) * 4 + b) * CDIM * NTOK;
    const float* K = g_qkv + ((size_t)(s == 0 ? 4 : 1) * 4 + b) * CDIM * NTOK;
    const float* V = g_qkv + ((size_t)(s == 0 ? 2 : 5) * 4 + b) * CDIM * NTOK;
    float* O = out + ((size_t)s * 4 + b) * CDIM * NTOK;   // [d][n]

    const int t  = threadIdx.x;
    const int tx = t & 15, ty = t >> 4;
    const int n0 = nt * BM;

    // Load Q tile [256][64]
    #pragma unroll
    for (int r = 0; r < 16; ++r) {
        const int d = r * 16 + ty;
        *(float4*)&Qs[d * 64 + tx * 4] =
            *(const float4*)&Q[(size_t)d * NTOK + n0 + tx * 4];
    }

    float o[4][16];
    #pragma unroll
    for (int i = 0; i < 4; ++i)
        #pragma unroll
        for (int c = 0; c < 16; ++c) o[i][c] = 0.0f;

    float m_i[4] = {-CUDART_INF_F, -CUDART_INF_F, -CUDART_INF_F, -CUDART_INF_F};
    float l_i[4] = {0.0f, 0.0f, 0.0f, 0.0f};

    for (int it = 0; it < NTOK / BN; ++it) {
        const int m0 = it * BN;
        __syncthreads();   // previous PV done before overwriting Ks/Vs

        // Load K tile [d][m] row=64, V tile [d][m] row=65
        #pragma unroll
        for (int r = 0; r < 16; ++r) {
            const int d = r * 16 + ty;
            *(float4*)&Ks[d * 64 + tx * 4] =
                *(const float4*)&K[(size_t)d * NTOK + m0 + tx * 4];
            const float4 vv = *(const float4*)&V[(size_t)d * NTOK + m0 + tx * 4];
            Vs[d * 65 + tx * 4 + 0] = vv.x;
            Vs[d * 65 + tx * 4 + 1] = vv.y;
            Vs[d * 65 + tx * 4 + 2] = vv.z;
            Vs[d * 65 + tx * 4 + 3] = vv.w;
        }
        __syncthreads();

        // S = Q^T K  (thread tile 4n x 4m)
        float sreg[4][4] = {};
        #pragma unroll 8
        for (int d = 0; d < CDIM; ++d) {
            const float4 qv = *(const float4*)&Qs[d * 64 + ty * 4];
            const float4 kv = *(const float4*)&Ks[d * 64 + tx * 4];
            const float qr[4] = {qv.x, qv.y, qv.z, qv.w};
            const float kr[4] = {kv.x, kv.y, kv.z, kv.w};
            #pragma unroll
            for (int i = 0; i < 4; ++i)
                #pragma unroll
                for (int j = 0; j < 4; ++j)
                    sreg[i][j] += qr[i] * kr[j];
        }

        // online softmax per row; reduce across 16 lanes sharing a row
        #pragma unroll
        for (int i = 0; i < 4; ++i) {
            float mx = fmaxf(fmaxf(sreg[i][0], sreg[i][1]),
                             fmaxf(sreg[i][2], sreg[i][3]));
            #pragma unroll
            for (int off = 1; off < 16; off <<= 1)
                mx = fmaxf(mx, __shfl_xor_sync(0xffffffffu, mx, off));

            const float mnew  = fmaxf(m_i[i], mx);
            const float alpha = __expf(m_i[i] - mnew);
            m_i[i] = mnew;

            float rs = 0.0f;
            #pragma unroll
            for (int j = 0; j < 4; ++j) {
                const float pj = __expf(sreg[i][j] - mnew);
                sreg[i][j] = pj;
                rs += pj;
            }
            #pragma unroll
            for (int off = 1; off < 16; off <<= 1)
                rs += __shfl_xor_sync(0xffffffffu, rs, off);
            l_i[i] = l_i[i] * alpha + rs;

            #pragma unroll
            for (int c = 0; c < 16; ++c) o[i][c] *= alpha;
        }

        // publish P tile
        #pragma unroll
        for (int i = 0; i < 4; ++i) {
            float4 pv;
            pv.x = sreg[i][0]; pv.y = sreg[i][1];
            pv.z = sreg[i][2]; pv.w = sreg[i][3];
            *(float4*)&Ps[(ty * 4 + i) * 64 + tx * 4] = pv;
        }
        __syncthreads();

        // O += P @ V^T : o[n][d] += sum_m P[n][m] * V[d][m]
        // thread owns n = ty*4+i (4), d = c*64 + tx*4 + jj (16)
        #pragma unroll 4
        for (int m = 0; m < BN; ++m) {
            float pr[4];
            #pragma unroll
            for (int i = 0; i < 4; ++i) pr[i] = Ps[(ty * 4 + i) * 64 + m];
            #pragma unroll
            for (int c = 0; c < 4; ++c) {
                #pragma unroll
                for (int jj = 0; jj < 4; ++jj) {
                    const float vv = Vs[(c * 64 + tx * 4 + jj) * 65 + m];
                    #pragma unroll
                    for (int i = 0; i < 4; ++i) o[i][c * 4 + jj] += pr[i] * vv;
                }
            }
        }
    }

    // normalize + write out[d][n] (float4 over 4 consecutive n)
    float inv[4];
    #pragma unroll
    for (int i = 0; i < 4; ++i) inv[i] = 1.0f / l_i[i];

    #pragma unroll
    for (int c = 0; c < 4; ++c) {
        #pragma unroll
        for (int jj = 0; jj < 4; ++jj) {
            const int d = c * 64 + tx * 4 + jj;
            float4 r;
            r.x = o[0][c * 4 + jj] * inv[0];
            r.y = o[1][c * 4 + jj] * inv[1];
            r.z = o[2][c * 4 + jj] * inv[2];
            r.w = o[3][c * 4 + jj] * inv[3];
            *(float4*)&O[(size_t)d * NTOK + n0 + ty * 4] = r;
        }
    }
}

// ---------------------------------------------------------------------------
extern "C" void kernel_launch(void* const* d_in, const int* in_sizes, int n_in,
                              void* d_out, int out_size)
{
    const float* x1 = (const float*)d_in[0];
    const float* x2 = (const float*)d_in[1];
    const float* Wq = (const float*)d_in[2];
    const float* bq = (const float*)d_in[3];
    const float* Wk = (const float*)d_in[4];
    const float* bk = (const float*)d_in[5];
    const float* Wv = (const float*)d_in[6];
    const float* bv = (const float*)d_in[7];
    float* out = (float*)d_out;

    (void)in_sizes; (void)n_in; (void)out_size;

    dim3 pg(NTOK / 64, CDIM / 64, 24);
    proj_kernel<<<pg, 256>>>(x1, x2, Wq, bq, Wk, bk, Wv, bv);

    cudaFuncSetAttribute(attn_kernel,
                         cudaFuncAttributeMaxDynamicSharedMemorySize, SMEM_BYTES);
    dim3 ag(NTOK / BM, 8);
    attn_kernel<<<ag, 256, SMEM_BYTES>>>(out);
}

// round 2
// speedup vs baseline: 1.0005x; 1.0005x over previous
#include <cuda_runtime.h>
#include <math_constants.h>

#define CDIM 256
#define NTOK 4096
#define BM 64
#define BN 64

// Scratch for Q1,K1,V1,Q2,K2,V2: [p][b][d][n], p in {0:q1,1:k1,2:v1,3:q2,4:k2,5:v2}
__device__ float g_qkv[6ull * 4 * CDIM * NTOK];

// ---------------------------------------------------------------------------
// Projection: out[p][b][d][n] = bias[d] + sum_c W[d][c] * x_s[b][c][n]
// grid: (N/64, C/64, 24=p*4+b), 256 threads, 64x64 tile, BK=16
// ---------------------------------------------------------------------------
__global__ __launch_bounds__(256) void proj_kernel(
    const float* __restrict__ x1, const float* __restrict__ x2,
    const float* __restrict__ Wq, const float* __restrict__ bq,
    const float* __restrict__ Wk, const float* __restrict__ bk,
    const float* __restrict__ Wv, const float* __restrict__ bv)
{
    __shared__ float Ws[16][64];   // Ws[c][d]
    __shared__ float Xs[16][64];   // Xs[c][n]

    const int nt = blockIdx.x;
    const int dt = blockIdx.y;
    const int z  = blockIdx.z;
    const int p = z >> 2, b = z & 3;
    const int s = p / 3, w = p % 3;

    const float* X    = (s == 0 ? x1 : x2) + (size_t)b * CDIM * NTOK;
    const float* W    = (w == 0 ? Wq : (w == 1 ? Wk : Wv));
    const float* bias = (w == 0 ? bq : (w == 1 ? bk : bv));
    float* out = g_qkv + ((size_t)p * 4 + b) * CDIM * NTOK;

    const int t  = threadIdx.x;
    const int tx = t & 15, ty = t >> 4;
    const int n0 = nt * 64, d0 = dt * 64;

    float acc[4][4] = {};

    for (int kk = 0; kk < CDIM; kk += 16) {
        // W tile: rows d (64), cols c (16) -> transposed into Ws[c][d]
        {
            const int dd = t >> 2, cc = (t & 3) * 4;
            float4 v = *(const float4*)(W + (size_t)(d0 + dd) * CDIM + kk + cc);
            Ws[cc + 0][dd] = v.x; Ws[cc + 1][dd] = v.y;
            Ws[cc + 2][dd] = v.z; Ws[cc + 3][dd] = v.w;
        }
        // X tile: Xs[c][n]
        {
            const int cc = t >> 4, nn = (t & 15) * 4;
            *(float4*)&Xs[cc][nn] =
                *(const float4*)(X + (size_t)(kk + cc) * NTOK + n0 + nn);
        }
        __syncthreads();

        #pragma unroll
        for (int c = 0; c < 16; ++c) {
            const float4 wv = *(const float4*)&Ws[c][ty * 4];
            const float4 xv = *(const float4*)&Xs[c][tx * 4];
            const float wr[4] = {wv.x, wv.y, wv.z, wv.w};
            const float xr[4] = {xv.x, xv.y, xv.z, xv.w};
            #pragma unroll
            for (int i = 0; i < 4; ++i)
                #pragma unroll
                for (int j = 0; j < 4; ++j)
                    acc[i][j] += wr[i] * xr[j];
        }
        __syncthreads();
    }

    #pragma unroll
    for (int i = 0; i < 4; ++i) {
        const float bb = bias[d0 + ty * 4 + i];
        float4 r;
        r.x = acc[i][0] + bb; r.y = acc[i][1] + bb;
        r.z = acc[i][2] + bb; r.w = acc[i][3] + bb;
        *(float4*)&out[(size_t)(d0 + ty * 4 + i) * NTOK + n0 + tx * 4] = r;
    }
}

// ---------------------------------------------------------------------------
// Flash attention, fp32.
// grid: (N/64, 8=s*4+b), 256 threads. One CTA = 64 query rows, full D=256.
// smem: Qs[256][64], Ks[256][64], Vs[256][65], Ps[64][64]  -> 214016 B
// ---------------------------------------------------------------------------
#define SM_Q 0
#define SM_K (256 * 64)
#define SM_V (2 * 256 * 64)
#define SM_P (2 * 256 * 64 + 256 * 65)
#define SMEM_FLOATS (2 * 256 * 64 + 256 * 65 + 64 * 64)
#define SMEM_BYTES (SMEM_FLOATS * 4)

__global__ __launch_bounds__(256) void attn_kernel(float* __restrict__ out)
{
    extern __shared__ float smem[];
    float* Qs = smem + SM_Q;   // [d][n]  row=64
    float* Ks = smem + SM_K;   // [d][m]  row=64
    float* Vs = smem + SM_V;   // [d][m]  row=65 (pad: scalar access pattern)
    float* Ps = smem + SM_P;   // [n][m]  row=64

    const int nt = blockIdx.x;
    const int z  = blockIdx.y;
    const int s = z >> 2, b = z & 3;

    // stream 0: q=q1(p0), k=k2(p4), v=v1(p2); stream 1: q=q2(p3), k=k1(p1), v=v2(p5)
    const float* Q = g_qkv + ((size_t)(s == 0 ? 0 : 3) * 4 + b) * CDIM * NTOK;
    const float* K = g_qkv + ((size_t)(s == 0 ? 4 : 1) * 4 + b) * CDIM * NTOK;
    const float* V = g_qkv + ((size_t)(s == 0 ? 2 : 5) * 4 + b) * CDIM * NTOK;
    float* O = out + ((size_t)s * 4 + b) * CDIM * NTOK;   // [d][n]

    const int t  = threadIdx.x;
    const int tx = t & 15, ty = t >> 4;
    const int n0 = nt * BM;

    // Load Q tile [256][64]
    #pragma unroll
    for (int r = 0; r < 16; ++r) {
        const int d = r * 16 + ty;
        *(float4*)&Qs[d * 64 + tx * 4] =
            *(const float4*)&Q[(size_t)d * NTOK + n0 + tx * 4];
    }

    float o[4][16];
    #pragma unroll
    for (int i = 0; i < 4; ++i)
        #pragma unroll
        for (int c = 0; c < 16; ++c) o[i][c] = 0.0f;

    float m_i[4] = {-CUDART_INF_F, -CUDART_INF_F, -CUDART_INF_F, -CUDART_INF_F};
    float l_i[4] = {0.0f, 0.0f, 0.0f, 0.0f};

    for (int it = 0; it < NTOK / BN; ++it) {
        const int m0 = it * BN;
        __syncthreads();   // previous PV done before overwriting Ks/Vs

        // Load K tile [d][m] row=64, V tile [d][m] row=65
        #pragma unroll
        for (int r = 0; r < 16; ++r) {
            const int d = r * 16 + ty;
            *(float4*)&Ks[d * 64 + tx * 4] =
                *(const float4*)&K[(size_t)d * NTOK + m0 + tx * 4];
            const float4 vv = *(const float4*)&V[(size_t)d * NTOK + m0 + tx * 4];
            Vs[d * 65 + tx * 4 + 0] = vv.x;
            Vs[d * 65 + tx * 4 + 1] = vv.y;
            Vs[d * 65 + tx * 4 + 2] = vv.z;
            Vs[d * 65 + tx * 4 + 3] = vv.w;
        }
        __syncthreads();

        // S = Q^T K  (thread tile 4n x 4m)
        float sreg[4][4] = {};
        #pragma unroll 8
        for (int d = 0; d < CDIM; ++d) {
            const float4 qv = *(const float4*)&Qs[d * 64 + ty * 4];
            const float4 kv = *(const float4*)&Ks[d * 64 + tx * 4];
            const float qr[4] = {qv.x, qv.y, qv.z, qv.w};
            const float kr[4] = {kv.x, kv.y, kv.z, kv.w};
            #pragma unroll
            for (int i = 0; i < 4; ++i)
                #pragma unroll
                for (int j = 0; j < 4; ++j)
                    sreg[i][j] += qr[i] * kr[j];
        }

        // online softmax per row; reduce across 16 lanes sharing a row
        #pragma unroll
        for (int i = 0; i < 4; ++i) {
            float mx = fmaxf(fmaxf(sreg[i][0], sreg[i][1]),
                             fmaxf(sreg[i][2], sreg[i][3]));
            #pragma unroll
            for (int off = 1; off < 16; off <<= 1)
                mx = fmaxf(mx, __shfl_xor_sync(0xffffffffu, mx, off));

            const float mnew  = fmaxf(m_i[i], mx);
            const float alpha = __expf(m_i[i] - mnew);
            m_i[i] = mnew;

            float rs = 0.0f;
            #pragma unroll
            for (int j = 0; j < 4; ++j) {
                const float pj = __expf(sreg[i][j] - mnew);
                sreg[i][j] = pj;
                rs += pj;
            }
            #pragma unroll
            for (int off = 1; off < 16; off <<= 1)
                rs += __shfl_xor_sync(0xffffffffu, rs, off);
            l_i[i] = l_i[i] * alpha + rs;

            #pragma unroll
            for (int c = 0; c < 16; ++c) o[i][c] *= alpha;
        }

        // publish P tile
        #pragma unroll
        for (int i = 0; i < 4; ++i) {
            float4 pv;
            pv.x = sreg[i][0]; pv.y = sreg[i][1];
            pv.z = sreg[i][2]; pv.w = sreg[i][3];
            *(float4*)&Ps[(ty * 4 + i) * 64 + tx * 4] = pv;
        }
        __syncthreads();

        // O += P @ V^T : o[n][d] += sum_m P[n][m] * V[d][m]
        // thread owns n = ty*4+i (4), d = c*64 + tx*4 + jj (16)
        #pragma unroll 4
        for (int m = 0; m < BN; ++m) {
            float pr[4];
            #pragma unroll
            for (int i = 0; i < 4; ++i) pr[i] = Ps[(ty * 4 + i) * 64 + m];
            #pragma unroll
            for (int c = 0; c < 4; ++c) {
                #pragma unroll
                for (int jj = 0; jj < 4; ++jj) {
                    const float vv = Vs[(c * 64 + tx * 4 + jj) * 65 + m];
                    #pragma unroll
                    for (int i = 0; i < 4; ++i) o[i][c * 4 + jj] += pr[i] * vv;
                }
            }
        }
    }

    // normalize + write out[d][n] (float4 over 4 consecutive n)
    float inv[4];
    #pragma unroll
    for (int i = 0; i < 4; ++i) inv[i] = 1.0f / l_i[i];

    #pragma unroll
    for (int c = 0; c < 4; ++c) {
        #pragma unroll
        for (int jj = 0; jj < 4; ++jj) {
            const int d = c * 64 + tx * 4 + jj;
            float4 r;
            r.x = o[0][c * 4 + jj] * inv[0];
            r.y = o[1][c * 4 + jj] * inv[1];
            r.z = o[2][c * 4 + jj] * inv[2];
            r.w = o[3][c * 4 + jj] * inv[3];
            *(float4*)&O[(size_t)d * NTOK + n0 + ty * 4] = r;
        }
    }
}

// ---------------------------------------------------------------------------
extern "C" void kernel_launch(void* const* d_in, const int* in_sizes, int n_in,
                              void* d_out, int out_size)
{
    const float* x1 = (const float*)d_in[0];
    const float* x2 = (const float*)d_in[1];
    const float* Wq = (const float*)d_in[2];
    const float* bq = (const float*)d_in[3];
    const float* Wk = (const float*)d_in[4];
    const float* bk = (const float*)d_in[5];
    const float* Wv = (const float*)d_in[6];
    const float* bv = (const float*)d_in[7];
    float* out = (float*)d_out;

    (void)in_sizes; (void)n_in; (void)out_size;

    dim3 pg(NTOK / 64, CDIM / 64, 24);
    proj_kernel<<<pg, 256>>>(x1, x2, Wq, bq, Wk, bk, Wv, bv);

    cudaFuncSetAttribute(attn_kernel,
                         cudaFuncAttributeMaxDynamicSharedMemorySize, SMEM_BYTES);
    dim3 ag(NTOK / BM, 8);
    attn_kernel<<<ag, 256, SMEM_BYTES>>>(out);
}

// round 3
// speedup vs baseline: 1.0063x; 1.0057x over previous
#include <cuda_runtime.h>
#include <math_constants.h>

#define CDIM 256
#define NTOK 4096
#define BM 64
#define BN 64

// Scratch for Q1,K1,V1,Q2,K2,V2: [p][b][d][n], p in {0:q1,1:k1,2:v1,3:q2,4:k2,5:v2}
__device__ float g_qkv[6ull * 4 * CDIM * NTOK];

// ---------------------------------------------------------------------------
// Projection: out[p][b][d][n] = bias[d] + sum_c W[d][c] * x_s[b][c][n]
// grid: (N/64, C/64, 24=p*4+b), 256 threads, 64x64 tile, BK=16
// ---------------------------------------------------------------------------
__global__ __launch_bounds__(256) void proj_kernel(
    const float* __restrict__ x1, const float* __restrict__ x2,
    const float* __restrict__ Wq, const float* __restrict__ bq,
    const float* __restrict__ Wk, const float* __restrict__ bk,
    const float* __restrict__ Wv, const float* __restrict__ bv)
{
    __shared__ float Ws[16][64];   // Ws[c][d]
    __shared__ float Xs[16][64];   // Xs[c][n]

    const int nt = blockIdx.x;
    const int dt = blockIdx.y;
    const int z  = blockIdx.z;
    const int p = z >> 2, b = z & 3;
    const int s = p / 3, w = p % 3;

    const float* X    = (s == 0 ? x1 : x2) + (size_t)b * CDIM * NTOK;
    const float* W    = (w == 0 ? Wq : (w == 1 ? Wk : Wv));
    const float* bias = (w == 0 ? bq : (w == 1 ? bk : bv));
    float* out = g_qkv + ((size_t)p * 4 + b) * CDIM * NTOK;

    const int t  = threadIdx.x;
    const int tx = t & 15, ty = t >> 4;
    const int n0 = nt * 64, d0 = dt * 64;

    float acc[4][4] = {};

    for (int kk = 0; kk < CDIM; kk += 16) {
        // W tile: rows d (64), cols c (16) -> transposed into Ws[c][d]
        {
            const int dd = t >> 2, cc = (t & 3) * 4;
            float4 v = *(const float4*)(W + (size_t)(d0 + dd) * CDIM + kk + cc);
            Ws[cc + 0][dd] = v.x; Ws[cc + 1][dd] = v.y;
            Ws[cc + 2][dd] = v.z; Ws[cc + 3][dd] = v.w;
        }
        // X tile: Xs[c][n]
        {
            const int cc = t >> 4, nn = (t & 15) * 4;
            *(float4*)&Xs[cc][nn] =
                *(const float4*)(X + (size_t)(kk + cc) * NTOK + n0 + nn);
        }
        __syncthreads();

        #pragma unroll
        for (int c = 0; c < 16; ++c) {
            const float4 wv = *(const float4*)&Ws[c][ty * 4];
            const float4 xv = *(const float4*)&Xs[c][tx * 4];
            const float wr[4] = {wv.x, wv.y, wv.z, wv.w};
            const float xr[4] = {xv.x, xv.y, xv.z, xv.w};
            #pragma unroll
            for (int i = 0; i < 4; ++i)
                #pragma unroll
                for (int j = 0; j < 4; ++j)
                    acc[i][j] += wr[i] * xr[j];
        }
        __syncthreads();
    }

    #pragma unroll
    for (int i = 0; i < 4; ++i) {
        const float bb = bias[d0 + ty * 4 + i];
        float4 r;
        r.x = acc[i][0] + bb; r.y = acc[i][1] + bb;
        r.z = acc[i][2] + bb; r.w = acc[i][3] + bb;
        *(float4*)&out[(size_t)(d0 + ty * 4 + i) * NTOK + n0 + tx * 4] = r;
    }
}

// ---------------------------------------------------------------------------
// Flash attention, fp32.
// grid: (N/64, 8=s*4+b), 256 threads. One CTA = 64 query rows, full D=256.
// smem: Qs[256][64], Ks[256][64], Vs[256][65], Ps[64][64]  -> 214016 B
// ---------------------------------------------------------------------------
#define SM_Q 0
#define SM_K (256 * 64)
#define SM_V (2 * 256 * 64)
#define SM_P (2 * 256 * 64 + 256 * 65)
#define SMEM_FLOATS (2 * 256 * 64 + 256 * 65 + 64 * 64)
#define SMEM_BYTES (SMEM_FLOATS * 4)

__global__ __launch_bounds__(256) void attn_kernel(float* __restrict__ out)
{
    extern __shared__ float smem[];
    float* Qs = smem + SM_Q;   // [d][n]  row=64
    float* Ks = smem + SM_K;   // [d][m]  row=64
    float* Vs = smem + SM_V;   // [d][m]  row=65 (pad: scalar access pattern)
    float* Ps = smem + SM_P;   // [n][m]  row=64

    const int nt = blockIdx.x;
    const int z  = blockIdx.y;
    const int s = z >> 2, b = z & 3;

    // stream 0: q=q1(p0), k=k2(p4), v=v1(p2); stream 1: q=q2(p3), k=k1(p1), v=v2(p5)
    const float* Q = g_qkv + ((size_t)(s == 0 ? 0 : 3) * 4 + b) * CDIM * NTOK;
    const float* K = g_qkv + ((size_t)(s == 0 ? 4 : 1) * 4 + b) * CDIM * NTOK;
    const float* V = g_qkv + ((size_t)(s == 0 ? 2 : 5) * 4 + b) * CDIM * NTOK;
    float* O = out + ((size_t)s * 4 + b) * CDIM * NTOK;   // [d][n]

    const int t  = threadIdx.x;
    const int tx = t & 15, ty = t >> 4;
    const int n0 = nt * BM;

    // Load Q tile [256][64]
    #pragma unroll
    for (int r = 0; r < 16; ++r) {
        const int d = r * 16 + ty;
        *(float4*)&Qs[d * 64 + tx * 4] =
            *(const float4*)&Q[(size_t)d * NTOK + n0 + tx * 4];
    }

    float o[4][16];
    #pragma unroll
    for (int i = 0; i < 4; ++i)
        #pragma unroll
        for (int c = 0; c < 16; ++c) o[i][c] = 0.0f;

    float m_i[4] = {-CUDART_INF_F, -CUDART_INF_F, -CUDART_INF_F, -CUDART_INF_F};
    float l_i[4] = {0.0f, 0.0f, 0.0f, 0.0f};

    for (int it = 0; it < NTOK / BN; ++it) {
        const int m0 = it * BN;
        __syncthreads();   // previous PV done before overwriting Ks/Vs

        // Load K tile [d][m] row=64, V tile [d][m] row=65
        #pragma unroll
        for (int r = 0; r < 16; ++r) {
            const int d = r * 16 + ty;
            *(float4*)&Ks[d * 64 + tx * 4] =
                *(const float4*)&K[(size_t)d * NTOK + m0 + tx * 4];
            const float4 vv = *(const float4*)&V[(size_t)d * NTOK + m0 + tx * 4];
            Vs[d * 65 + tx * 4 + 0] = vv.x;
            Vs[d * 65 + tx * 4 + 1] = vv.y;
            Vs[d * 65 + tx * 4 + 2] = vv.z;
            Vs[d * 65 + tx * 4 + 3] = vv.w;
        }
        __syncthreads();

        // S = Q^T K  (thread tile 4n x 4m)
        float sreg[4][4] = {};
        #pragma unroll 8
        for (int d = 0; d < CDIM; ++d) {
            const float4 qv = *(const float4*)&Qs[d * 64 + ty * 4];
            const float4 kv = *(const float4*)&Ks[d * 64 + tx * 4];
            const float qr[4] = {qv.x, qv.y, qv.z, qv.w};
            const float kr[4] = {kv.x, kv.y, kv.z, kv.w};
            #pragma unroll
            for (int i = 0; i < 4; ++i)
                #pragma unroll
                for (int j = 0; j < 4; ++j)
                    sreg[i][j] += qr[i] * kr[j];
        }

        // online softmax per row; reduce across 16 lanes sharing a row
        #pragma unroll
        for (int i = 0; i < 4; ++i) {
            float mx = fmaxf(fmaxf(sreg[i][0], sreg[i][1]),
                             fmaxf(sreg[i][2], sreg[i][3]));
            #pragma unroll
            for (int off = 1; off < 16; off <<= 1)
                mx = fmaxf(mx, __shfl_xor_sync(0xffffffffu, mx, off));

            const float mnew  = fmaxf(m_i[i], mx);
            const float alpha = __expf(m_i[i] - mnew);
            m_i[i] = mnew;

            float rs = 0.0f;
            #pragma unroll
            for (int j = 0; j < 4; ++j) {
                const float pj = __expf(sreg[i][j] - mnew);
                sreg[i][j] = pj;
                rs += pj;
            }
            #pragma unroll
            for (int off = 1; off < 16; off <<= 1)
                rs += __shfl_xor_sync(0xffffffffu, rs, off);
            l_i[i] = l_i[i] * alpha + rs;

            #pragma unroll
            for (int c = 0; c < 16; ++c) o[i][c] *= alpha;
        }

        // publish P tile
        #pragma unroll
        for (int i = 0; i < 4; ++i) {
            float4 pv;
            pv.x = sreg[i][0]; pv.y = sreg[i][1];
            pv.z = sreg[i][2]; pv.w = sreg[i][3];
            *(float4*)&Ps[(ty * 4 + i) * 64 + tx * 4] = pv;
        }
        __syncthreads();

        // O += P @ V^T : o[n][d] += sum_m P[n][m] * V[d][m]
        // thread owns n = ty*4+i (4), d = c*64 + tx*4 + jj (16)
        #pragma unroll 4
        for (int m = 0; m < BN; ++m) {
            float pr[4];
            #pragma unroll
            for (int i = 0; i < 4; ++i) pr[i] = Ps[(ty * 4 + i) * 64 + m];
            #pragma unroll
            for (int c = 0; c < 4; ++c) {
                #pragma unroll
                for (int jj = 0; jj < 4; ++jj) {
                    const float vv = Vs[(c * 64 + tx * 4 + jj) * 65 + m];
                    #pragma unroll
                    for (int i = 0; i < 4; ++i) o[i][c * 4 + jj] += pr[i] * vv;
                }
            }
        }
    }

    // normalize + write out[d][n] (float4 over 4 consecutive n)
    float inv[4];
    #pragma unroll
    for (int i = 0; i < 4; ++i) inv[i] = 1.0f / l_i[i];

    #pragma unroll
    for (int c = 0; c < 4; ++c) {
        #pragma unroll
        for (int jj = 0; jj < 4; ++jj) {
            const int d = c * 64 + tx * 4 + jj;
            float4 r;
            r.x = o[0][c * 4 + jj] * inv[0];
            r.y = o[1][c * 4 + jj] * inv[1];
            r.z = o[2][c * 4 + jj] * inv[2];
            r.w = o[3][c * 4 + jj] * inv[3];
            *(float4*)&O[(size_t)d * NTOK + n0 + ty * 4] = r;
        }
    }
}

// ---------------------------------------------------------------------------
extern "C" void kernel_launch(void* const* d_in, const int* in_sizes, int n_in,
                              void* d_out, int out_size)
{
    const float* x1 = (const float*)d_in[0];
    const float* x2 = (const float*)d_in[1];
    const float* Wq = (const float*)d_in[2];
    const float* bq = (const float*)d_in[3];
    const float* Wk = (const float*)d_in[4];
    const float* bk = (const float*)d_in[5];
    const float* Wv = (const float*)d_in[6];
    const float* bv = (const float*)d_in[7];
    float* out = (float*)d_out;

    (void)in_sizes; (void)n_in; (void)out_size;

    dim3 pg(NTOK / 64, CDIM / 64, 24);
    proj_kernel<<<pg, 256>>>(x1, x2, Wq, bq, Wk, bk, Wv, bv);

    cudaFuncSetAttribute(attn_kernel,
                         cudaFuncAttributeMaxDynamicSharedMemorySize, SMEM_BYTES);
    dim3 ag(NTOK / BM, 8);
    attn_kernel<<<ag, 256, SMEM_BYTES>>>(out);
}

// round 4
// speedup vs baseline: 2.0375x; 2.0248x over previous
#include <cuda_runtime.h>
#include <cuda_fp16.h>
#include <math_constants.h>
#include <cstdint>

#define CDIM 256
#define NTOK 4096
#define BM 128
#define BN 32

// Split fp16 operand tensors (hi + lo ~= fp32 value).
// Q,K: [sb][n][d] (d contiguous)  V: [sb][d][n] (n contiguous); sb = s*4+b
__device__ __half g_qh[2ull * 4 * NTOK * CDIM];
__device__ __half g_ql[2ull * 4 * NTOK * CDIM];
__device__ __half g_kh[2ull * 4 * NTOK * CDIM];
__device__ __half g_kl[2ull * 4 * NTOK * CDIM];
__device__ __half g_vh[2ull * 4 * CDIM * NTOK];
__device__ __half g_vl[2ull * 4 * CDIM * NTOK];

__device__ __forceinline__ void split4(const float* f, uint2& hi, uint2& lo) {
    __half2 h0 = __floats2half2_rn(f[0], f[1]);
    __half2 h1 = __floats2half2_rn(f[2], f[3]);
    float2 a = __half22float2(h0), c = __half22float2(h1);
    __half2 l0 = __floats2half2_rn(f[0] - a.x, f[1] - a.y);
    __half2 l1 = __floats2half2_rn(f[2] - c.x, f[3] - c.y);
    hi = make_uint2(*(uint32_t*)&h0, *(uint32_t*)&h1);
    lo = make_uint2(*(uint32_t*)&l0, *(uint32_t*)&l1);
}

// ---------------------------------------------------------------------------
// Projection: val[d][n] = bias[d] + sum_c W[d][c] * x_s[b][c][n]
// writes split fp16: Q,K transposed to [n][d]; V kept [d][n].
// grid: (N/64, C/64, 24 = p*4+b), 256 threads
// ---------------------------------------------------------------------------
__global__ __launch_bounds__(256) void proj_kernel(
    const float* __restrict__ x1, const float* __restrict__ x2,
    const float* __restrict__ Wq, const float* __restrict__ bq,
    const float* __restrict__ Wk, const float* __restrict__ bk,
    const float* __restrict__ Wv, const float* __restrict__ bv)
{
    __shared__ float Ws[16][64];
    __shared__ float Xs[16][64];
    __shared__ float stage[16][68];

    const int nt = blockIdx.x;
    const int dt = blockIdx.y;
    const int z  = blockIdx.z;
    const int p = z >> 2, b = z & 3;
    const int s = p / 3, w = p % 3;

    const float* X    = (s == 0 ? x1 : x2) + (size_t)b * CDIM * NTOK;
    const float* W    = (w == 0 ? Wq : (w == 1 ? Wk : Wv));
    const float* bias = (w == 0 ? bq : (w == 1 ? bk : bv));

    const int t  = threadIdx.x;
    const int tx = t & 15, ty = t >> 4;
    const int n0 = nt * 64, d0 = dt * 64;

    float acc[4][4] = {};

    for (int kk = 0; kk < CDIM; kk += 16) {
        {
            const int dd = t >> 2, cc = (t & 3) * 4;
            float4 v = *(const float4*)(W + (size_t)(d0 + dd) * CDIM + kk + cc);
            Ws[cc + 0][dd] = v.x; Ws[cc + 1][dd] = v.y;
            Ws[cc + 2][dd] = v.z; Ws[cc + 3][dd] = v.w;
        }
        {
            const int cc = t >> 4, nn = (t & 15) * 4;
            *(float4*)&Xs[cc][nn] =
                *(const float4*)(X + (size_t)(kk + cc) * NTOK + n0 + nn);
        }
        __syncthreads();

        #pragma unroll
        for (int c = 0; c < 16; ++c) {
            const float4 wv = *(const float4*)&Ws[c][ty * 4];
            const float4 xv = *(const float4*)&Xs[c][tx * 4];
            const float wr[4] = {wv.x, wv.y, wv.z, wv.w};
            const float xr[4] = {xv.x, xv.y, xv.z, xv.w};
            #pragma unroll
            for (int i = 0; i < 4; ++i)
                #pragma unroll
                for (int j = 0; j < 4; ++j)
                    acc[i][j] += wr[i] * xr[j];
        }
        __syncthreads();
    }

    // add bias
    #pragma unroll
    for (int i = 0; i < 4; ++i) {
        const float bb = bias[d0 + ty * 4 + i];
        #pragma unroll
        for (int j = 0; j < 4; ++j) acc[i][j] += bb;
    }

    const size_t sb = (size_t)(s * 4 + b);

    if (w == 2) {
        // V: [d][n] split, coalesced store
        __half* vh = g_vh + sb * CDIM * NTOK;
        __half* vl = g_vl + sb * CDIM * NTOK;
        #pragma unroll
        for (int i = 0; i < 4; ++i) {
            const size_t base = (size_t)(d0 + ty * 4 + i) * NTOK + n0 + tx * 4;
            uint2 hi, lo;
            split4(acc[i], hi, lo);
            *(uint2*)&vh[base] = hi;
            *(uint2*)&vl[base] = lo;
        }
    } else {
        // Q,K: transpose to [n][d] via smem staging (4 chunks of 16 d)
        __half* oh = (w == 0 ? g_qh : g_kh) + sb * NTOK * CDIM;
        __half* ol = (w == 0 ? g_ql : g_kl) + sb * NTOK * CDIM;
        for (int c4 = 0; c4 < 4; ++c4) {
            __syncthreads();
            if ((ty >> 2) == c4) {
                #pragma unroll
                for (int i = 0; i < 4; ++i)
                    #pragma unroll
                    for (int j = 0; j < 4; ++j)
                        stage[(ty & 3) * 4 + i][tx * 4 + j] = acc[i][j];
            }
            __syncthreads();
            const int n = t >> 2, dq = (t & 3) * 4;
            float f[4];
            #pragma unroll
            for (int k = 0; k < 4; ++k) f[k] = stage[dq + k][n];
            uint2 hi, lo;
            split4(f, hi, lo);
            const size_t base = (size_t)(n0 + n) * CDIM + d0 + c4 * 16 + dq;
            *(uint2*)&oh[base] = hi;
            *(uint2*)&ol[base] = lo;
        }
    }
}

// ---------------------------------------------------------------------------
// Flash attention with mma.sync m16n8k16 fp16-split (hh + hl + lh).
// CTA = 128 query rows, 8 warps (16 rows each, full row ownership),
// BN=32 keys/iter, D=256 accumulated in registers.
// ---------------------------------------------------------------------------
#define QROW 264
#define KROW 264
#define VROW 40
#define OFF_QH 0
#define OFF_QL (128 * QROW)
#define OFF_KH (2 * 128 * QROW)
#define OFF_KL (OFF_KH + 32 * KROW)
#define OFF_VH (OFF_KL + 32 * KROW)
#define OFF_VL (OFF_VH + 256 * VROW)
#define SMEM_HALVES (OFF_VL + 256 * VROW)
#define ATTN_SMEM_BYTES (SMEM_HALVES * 2)

__device__ __forceinline__ void ldsm4(uint32_t* r, uint32_t a) {
    asm volatile("ldmatrix.sync.aligned.m8n8.x4.shared.b16 {%0,%1,%2,%3}, [%4];"
        : "=r"(r[0]), "=r"(r[1]), "=r"(r[2]), "=r"(r[3]) : "r"(a));
}
__device__ __forceinline__ void ldsm2(uint32_t* r, uint32_t a) {
    asm volatile("ldmatrix.sync.aligned.m8n8.x2.shared.b16 {%0,%1}, [%2];"
        : "=r"(r[0]), "=r"(r[1]) : "r"(a));
}
__device__ __forceinline__ void mma16816(float* c, const uint32_t* a, const uint32_t* b) {
    asm volatile(
        "mma.sync.aligned.m16n8k16.row.col.f32.f16.f16.f32 "
        "{%0,%1,%2,%3}, {%4,%5,%6,%7}, {%8,%9}, {%0,%1,%2,%3};"
        : "+f"(c[0]), "+f"(c[1]), "+f"(c[2]), "+f"(c[3])
        : "r"(a[0]), "r"(a[1]), "r"(a[2]), "r"(a[3]), "r"(b[0]), "r"(b[1]));
}
__device__ __forceinline__ void split2(float x, float y, uint32_t& hi, uint32_t& lo) {
    __half2 h = __floats2half2_rn(x, y);
    float2 hf = __half22float2(h);
    __half2 l = __floats2half2_rn(x - hf.x, y - hf.y);
    hi = *(uint32_t*)&h;
    lo = *(uint32_t*)&l;
}

__global__ __launch_bounds__(256, 1) void attn_kernel(float* __restrict__ out)
{
    extern __shared__ __half sm[];
    const int t = threadIdx.x, lane = t & 31, wid = t >> 5;
    const int ntile_blk = blockIdx.x, z = blockIdx.y;
    const int s = z >> 2, b = z & 3;
    const size_t sb  = (size_t)(s * 4 + b);
    const size_t sbk = (size_t)((1 - s) * 4 + b);

    const __half* Qh = g_qh + sb  * (size_t)NTOK * CDIM;
    const __half* Ql = g_ql + sb  * (size_t)NTOK * CDIM;
    const __half* Kh = g_kh + sbk * (size_t)NTOK * CDIM;
    const __half* Kl = g_kl + sbk * (size_t)NTOK * CDIM;
    const __half* Vh = g_vh + sb  * (size_t)CDIM * NTOK;
    const __half* Vl = g_vl + sb  * (size_t)CDIM * NTOK;
    float* O = out + sb * (size_t)CDIM * NTOK;

    const int n0 = ntile_blk * BM;

    // ---- load Q tile [128][256] hi/lo ----
    {
        const int row = t >> 1, seg = (t & 1) * 128;
        const uint4* gh = (const uint4*)&Qh[(size_t)(n0 + row) * CDIM + seg];
        const uint4* gl = (const uint4*)&Ql[(size_t)(n0 + row) * CDIM + seg];
        uint4* shp = (uint4*)&sm[OFF_QH + row * QROW + seg];
        uint4* slp = (uint4*)&sm[OFF_QL + row * QROW + seg];
        #pragma unroll
        for (int k = 0; k < 16; ++k) { shp[k] = gh[k]; slp[k] = gl[k]; }
    }

    const int nb = wid * 16;   // warp's 16 query rows
    const uint32_t smbase = (uint32_t)__cvta_generic_to_shared(sm);
    const uint32_t aq_h = smbase + (uint32_t)(OFF_QH + (nb + (lane & 15)) * QROW + ((lane >> 4) << 3)) * 2;
    const uint32_t aq_l = smbase + (uint32_t)(OFF_QL + (nb + (lane & 15)) * QROW + ((lane >> 4) << 3)) * 2;
    const uint32_t bk_h = smbase + (uint32_t)(OFF_KH + (lane & 7) * KROW + (((lane >> 3) & 1) << 3)) * 2;
    const uint32_t bk_l = smbase + (uint32_t)(OFF_KL + (lane & 7) * KROW + (((lane >> 3) & 1) << 3)) * 2;
    const uint32_t bv_h = smbase + (uint32_t)(OFF_VH + (lane & 7) * VROW + (((lane >> 3) & 1) << 3)) * 2;
    const uint32_t bv_l = smbase + (uint32_t)(OFF_VL + (lane & 7) * VROW + (((lane >> 3) & 1) << 3)) * 2;

    float o[32][4];
    #pragma unroll
    for (int dt = 0; dt < 32; ++dt)
        #pragma unroll
        for (int q = 0; q < 4; ++q) o[dt][q] = 0.0f;

    float mrow[2] = {-CUDART_INF_F, -CUDART_INF_F};
    float lsum[2] = {0.0f, 0.0f};

    for (int it = 0; it < NTOK / BN; ++it) {
        const int mb = it * BN;
        __syncthreads();
        // K tile: 32 rows x 256 halves per plane
        {
            const int row = t >> 3, seg = (t & 7) * 32;
            const uint4* gh = (const uint4*)&Kh[(size_t)(mb + row) * CDIM + seg];
            const uint4* gl = (const uint4*)&Kl[(size_t)(mb + row) * CDIM + seg];
            uint4* shp = (uint4*)&sm[OFF_KH + row * KROW + seg];
            uint4* slp = (uint4*)&sm[OFF_KL + row * KROW + seg];
            #pragma unroll
            for (int k = 0; k < 4; ++k) { shp[k] = gh[k]; slp[k] = gl[k]; }
        }
        // V tile: 256 rows x 32 halves per plane
        {
            const uint4* gh = (const uint4*)&Vh[(size_t)t * NTOK + mb];
            const uint4* gl = (const uint4*)&Vl[(size_t)t * NTOK + mb];
            uint4* shp = (uint4*)&sm[OFF_VH + t * VROW];
            uint4* slp = (uint4*)&sm[OFF_VL + t * VROW];
            #pragma unroll
            for (int k = 0; k < 4; ++k) { shp[k] = gh[k]; slp[k] = gl[k]; }
        }
        __syncthreads();

        // ---- S = Q K^T : warp tile 16 x 32 ----
        float sc[4][4];
        #pragma unroll
        for (int n8 = 0; n8 < 4; ++n8)
            #pragma unroll
            for (int q = 0; q < 4; ++q) sc[n8][q] = 0.0f;

        #pragma unroll
        for (int ks = 0; ks < 16; ++ks) {
            uint32_t aH[4], aL[4];
            ldsm4(aH, aq_h + ks * 32);
            ldsm4(aL, aq_l + ks * 32);
            #pragma unroll
            for (int n8 = 0; n8 < 4; ++n8) {
                uint32_t bH[2], bL[2];
                ldsm2(bH, bk_h + (uint32_t)(n8 * 8 * KROW) * 2 + ks * 32);
                ldsm2(bL, bk_l + (uint32_t)(n8 * 8 * KROW) * 2 + ks * 32);
                mma16816(sc[n8], aH, bH);
                mma16816(sc[n8], aH, bL);
                mma16816(sc[n8], aL, bH);
            }
        }

        // ---- online softmax (rows owned entirely by this warp) ----
        float alpha[2];
        #pragma unroll
        for (int h = 0; h < 2; ++h) {
            float mx = -CUDART_INF_F;
            #pragma unroll
            for (int n8 = 0; n8 < 4; ++n8)
                mx = fmaxf(mx, fmaxf(sc[n8][2 * h], sc[n8][2 * h + 1]));
            mx = fmaxf(mx, __shfl_xor_sync(0xffffffffu, mx, 1));
            mx = fmaxf(mx, __shfl_xor_sync(0xffffffffu, mx, 2));
            const float mnew = fmaxf(mrow[h], mx);
            alpha[h] = __expf(mrow[h] - mnew);
            mrow[h] = mnew;
            float rs = 0.0f;
            #pragma unroll
            for (int n8 = 0; n8 < 4; ++n8) {
                const float p0 = __expf(sc[n8][2 * h]     - mnew);
                const float p1 = __expf(sc[n8][2 * h + 1] - mnew);
                sc[n8][2 * h] = p0; sc[n8][2 * h + 1] = p1;
                rs += p0 + p1;
            }
            rs += __shfl_xor_sync(0xffffffffu, rs, 1);
            rs += __shfl_xor_sync(0xffffffffu, rs, 2);
            lsum[h] = lsum[h] * alpha[h] + rs;
        }
        #pragma unroll
        for (int dt = 0; dt < 32; ++dt) {
            o[dt][0] *= alpha[0]; o[dt][1] *= alpha[0];
            o[dt][2] *= alpha[1]; o[dt][3] *= alpha[1];
        }

        // ---- P fragments (A-layout, split hi/lo) ----
        uint32_t pah[2][4], pal[2][4];
        #pragma unroll
        for (int kc = 0; kc < 2; ++kc) {
            const int t0 = kc * 2, t1 = kc * 2 + 1;
            split2(sc[t0][0], sc[t0][1], pah[kc][0], pal[kc][0]);
            split2(sc[t0][2], sc[t0][3], pah[kc][1], pal[kc][1]);
            split2(sc[t1][0], sc[t1][1], pah[kc][2], pal[kc][2]);
            split2(sc[t1][2], sc[t1][3], pah[kc][3], pal[kc][3]);
        }

        // ---- O += P V : 32 d-tiles ----
        #pragma unroll
        for (int kc = 0; kc < 2; ++kc) {
            #pragma unroll
            for (int dt = 0; dt < 32; ++dt) {
                uint32_t bH[2], bL[2];
                ldsm2(bH, bv_h + (uint32_t)(dt * 8 * VROW) * 2 + kc * 32);
                ldsm2(bL, bv_l + (uint32_t)(dt * 8 * VROW) * 2 + kc * 32);
                mma16816(o[dt], pah[kc], bH);
                mma16816(o[dt], pah[kc], bL);
                mma16816(o[dt], pal[kc], bH);
            }
        }
    }

    // ---- epilogue: normalize, write out[d][n] ----
    const float inv0 = 1.0f / lsum[0];
    const float inv1 = 1.0f / lsum[1];
    const int r = lane >> 2, cc = (lane & 3) * 2;
    #pragma unroll
    for (int dt = 0; dt < 32; ++dt) {
        const int d = dt * 8 + cc;
        const size_t base = (size_t)d * NTOK + n0 + nb;
        O[base + r]            = o[dt][0] * inv0;
        O[base + NTOK + r]     = o[dt][1] * inv0;
        O[base + r + 8]        = o[dt][2] * inv1;
        O[base + NTOK + r + 8] = o[dt][3] * inv1;
    }
}

// ---------------------------------------------------------------------------
extern "C" void kernel_launch(void* const* d_in, const int* in_sizes, int n_in,
                              void* d_out, int out_size)
{
    const float* x1 = (const float*)d_in[0];
    const float* x2 = (const float*)d_in[1];
    const float* Wq = (const float*)d_in[2];
    const float* bq = (const float*)d_in[3];
    const float* Wk = (const float*)d_in[4];
    const float* bk = (const float*)d_in[5];
    const float* Wv = (const float*)d_in[6];
    const float* bv = (const float*)d_in[7];
    float* out = (float*)d_out;

    (void)in_sizes; (void)n_in; (void)out_size;

    dim3 pg(NTOK / 64, CDIM / 64, 24);
    proj_kernel<<<pg, 256>>>(x1, x2, Wq, bq, Wk, bk, Wv, bv);

    cudaFuncSetAttribute(attn_kernel,
                         cudaFuncAttributeMaxDynamicSharedMemorySize, ATTN_SMEM_BYTES);
    dim3 ag(NTOK / BM, 8);
    attn_kernel<<<ag, 256, ATTN_SMEM_BYTES>>>(out);
}

// round 5
// speedup vs baseline: 2.9703x; 1.4578x over previous
#include <cuda_runtime.h>
#include <cuda_fp16.h>
#include <math_constants.h>
#include <cstdint>

#define CDIM 256
#define NTOK 4096
#define BM 128
#define BN 32
#define ITERS (NTOK / BN)

// Split fp16 operand tensors (hi + lo ~= fp32). ALL stored [sb][n][d], d contiguous.
__device__ __half g_qh[2ull * 4 * NTOK * CDIM];
__device__ __half g_ql[2ull * 4 * NTOK * CDIM];
__device__ __half g_kh[2ull * 4 * NTOK * CDIM];
__device__ __half g_kl[2ull * 4 * NTOK * CDIM];
__device__ __half g_vh[2ull * 4 * NTOK * CDIM];
__device__ __half g_vl[2ull * 4 * NTOK * CDIM];

__device__ __forceinline__ void split4(const float* f, uint2& hi, uint2& lo) {
    __half2 h0 = __floats2half2_rn(f[0], f[1]);
    __half2 h1 = __floats2half2_rn(f[2], f[3]);
    float2 a = __half22float2(h0), c = __half22float2(h1);
    __half2 l0 = __floats2half2_rn(f[0] - a.x, f[1] - a.y);
    __half2 l1 = __floats2half2_rn(f[2] - c.x, f[3] - c.y);
    hi = make_uint2(*(uint32_t*)&h0, *(uint32_t*)&h1);
    lo = make_uint2(*(uint32_t*)&l0, *(uint32_t*)&l1);
}

// ---------------------------------------------------------------------------
// Projection: val[d][n] = bias[d] + sum_c W[d][c] * x_s[b][c][n]
// All outputs (Q,K,V) written transposed to [n][d], split hi/lo fp16.
// ---------------------------------------------------------------------------
__global__ __launch_bounds__(256) void proj_kernel(
    const float* __restrict__ x1, const float* __restrict__ x2,
    const float* __restrict__ Wq, const float* __restrict__ bq,
    const float* __restrict__ Wk, const float* __restrict__ bk,
    const float* __restrict__ Wv, const float* __restrict__ bv)
{
    __shared__ float Ws[16][64];
    __shared__ float Xs[16][64];
    __shared__ float stage[16][68];

    const int nt = blockIdx.x;
    const int dt = blockIdx.y;
    const int z  = blockIdx.z;
    const int p = z >> 2, b = z & 3;
    const int s = p / 3, w = p % 3;

    const float* X    = (s == 0 ? x1 : x2) + (size_t)b * CDIM * NTOK;
    const float* W    = (w == 0 ? Wq : (w == 1 ? Wk : Wv));
    const float* bias = (w == 0 ? bq : (w == 1 ? bk : bv));

    const int t  = threadIdx.x;
    const int tx = t & 15, ty = t >> 4;
    const int n0 = nt * 64, d0 = dt * 64;

    float acc[4][4] = {};

    for (int kk = 0; kk < CDIM; kk += 16) {
        {
            const int dd = t >> 2, cc = (t & 3) * 4;
            float4 v = *(const float4*)(W + (size_t)(d0 + dd) * CDIM + kk + cc);
            Ws[cc + 0][dd] = v.x; Ws[cc + 1][dd] = v.y;
            Ws[cc + 2][dd] = v.z; Ws[cc + 3][dd] = v.w;
        }
        {
            const int cc = t >> 4, nn = (t & 15) * 4;
            *(float4*)&Xs[cc][nn] =
                *(const float4*)(X + (size_t)(kk + cc) * NTOK + n0 + nn);
        }
        __syncthreads();

        #pragma unroll
        for (int c = 0; c < 16; ++c) {
            const float4 wv = *(const float4*)&Ws[c][ty * 4];
            const float4 xv = *(const float4*)&Xs[c][tx * 4];
            const float wr[4] = {wv.x, wv.y, wv.z, wv.w};
            const float xr[4] = {xv.x, xv.y, xv.z, xv.w};
            #pragma unroll
            for (int i = 0; i < 4; ++i)
                #pragma unroll
                for (int j = 0; j < 4; ++j)
                    acc[i][j] += wr[i] * xr[j];
        }
        __syncthreads();
    }

    #pragma unroll
    for (int i = 0; i < 4; ++i) {
        const float bb = bias[d0 + ty * 4 + i];
        #pragma unroll
        for (int j = 0; j < 4; ++j) acc[i][j] += bb;
    }

    const size_t sb = (size_t)(s * 4 + b);
    __half* oh = (w == 0 ? g_qh : (w == 1 ? g_kh : g_vh)) + sb * (size_t)NTOK * CDIM;
    __half* ol = (w == 0 ? g_ql : (w == 1 ? g_kl : g_vl)) + sb * (size_t)NTOK * CDIM;

    // transpose to [n][d] via smem staging (4 chunks of 16 d)
    for (int c4 = 0; c4 < 4; ++c4) {
        __syncthreads();
        if ((ty >> 2) == c4) {
            #pragma unroll
            for (int i = 0; i < 4; ++i)
                #pragma unroll
                for (int j = 0; j < 4; ++j)
                    stage[(ty & 3) * 4 + i][tx * 4 + j] = acc[i][j];
        }
        __syncthreads();
        const int n = t >> 2, dq = (t & 3) * 4;
        float f[4];
        #pragma unroll
        for (int k = 0; k < 4; ++k) f[k] = stage[dq + k][n];
        uint2 hi, lo;
        split4(f, hi, lo);
        const size_t base = (size_t)(n0 + n) * CDIM + d0 + c4 * 16 + dq;
        *(uint2*)&oh[base] = hi;
        *(uint2*)&ol[base] = lo;
    }
}

// ---------------------------------------------------------------------------
// Flash attention, mma.sync m16n8k16 fp16-split, cp.async pipelined,
// XOR-swizzled smem (no padding), ldmatrix x4 merged fragments.
// smem layout (halves): Qh[0,32768) Ql[32768,65536)
//                       K stages [65536 + stg*16384): hi 8192 + lo 8192
//                       V [98304): hi 8192 + lo 8192   => 229376 bytes total
// ---------------------------------------------------------------------------
#define OFF_QH 0
#define OFF_QL 32768
#define OFF_K  65536
#define KSTG   16384
#define OFF_V  98304
#define SMEM_HALVES 114688
#define ATTN_SMEM_BYTES (SMEM_HALVES * 2)

__device__ __forceinline__ void cpa16(uint32_t dst, const void* src) {
    asm volatile("cp.async.cg.shared.global [%0], [%1], 16;" :: "r"(dst), "l"(src));
}
#define CPA_COMMIT() asm volatile("cp.async.commit_group;")
#define CPA_WAIT1()  asm volatile("cp.async.wait_group 1;")

__device__ __forceinline__ void ldsm4(uint32_t* r, uint32_t a) {
    asm volatile("ldmatrix.sync.aligned.m8n8.x4.shared.b16 {%0,%1,%2,%3}, [%4];"
        : "=r"(r[0]), "=r"(r[1]), "=r"(r[2]), "=r"(r[3]) : "r"(a));
}
__device__ __forceinline__ void ldsm4t(uint32_t* r, uint32_t a) {
    asm volatile("ldmatrix.sync.aligned.m8n8.x4.trans.shared.b16 {%0,%1,%2,%3}, [%4];"
        : "=r"(r[0]), "=r"(r[1]), "=r"(r[2]), "=r"(r[3]) : "r"(a));
}
__device__ __forceinline__ void mma16816(float* c, const uint32_t* a, const uint32_t* b) {
    asm volatile(
        "mma.sync.aligned.m16n8k16.row.col.f32.f16.f16.f32 "
        "{%0,%1,%2,%3}, {%4,%5,%6,%7}, {%8,%9}, {%0,%1,%2,%3};"
        : "+f"(c[0]), "+f"(c[1]), "+f"(c[2]), "+f"(c[3])
        : "r"(a[0]), "r"(a[1]), "r"(a[2]), "r"(a[3]), "r"(b[0]), "r"(b[1]));
}
__device__ __forceinline__ void split2(float x, float y, uint32_t& hi, uint32_t& lo) {
    __half2 h = __floats2half2_rn(x, y);
    float2 hf = __half22float2(h);
    __half2 l = __floats2half2_rn(x - hf.x, y - hf.y);
    hi = *(uint32_t*)&h;
    lo = *(uint32_t*)&l;
}

// Load a 32-row x 256-half tile (hi+lo planes) into swizzled smem via cp.async.
__device__ __forceinline__ void load_tile32(
    uint32_t smbase, int offH, const __half* __restrict__ srcH,
    const __half* __restrict__ srcL, int mb, int t)
{
    #pragma unroll
    for (int k = 0; k < 4; ++k) {
        const int chunk = k * 256 + t;
        const int row = chunk >> 5, c = chunk & 31;
        const int swz = ((c ^ (row & 7)) << 3);
        const size_t g = (size_t)(mb + row) * CDIM + c * 8;
        cpa16(smbase + (uint32_t)((offH + row * 256 + swz) << 1), srcH + g);
        cpa16(smbase + (uint32_t)((offH + 8192 + row * 256 + swz) << 1), srcL + g);
    }
}

__global__ __launch_bounds__(256, 1) void attn_kernel(float* __restrict__ out)
{
    extern __shared__ __half sm[];
    const int t = threadIdx.x, lane = t & 31, wid = t >> 5;
    const int z = blockIdx.y;
    const int s = z >> 2, b = z & 3;
    const size_t sb  = (size_t)(s * 4 + b);
    const size_t sbk = (size_t)((1 - s) * 4 + b);

    const __half* Qh = g_qh + sb  * (size_t)NTOK * CDIM;
    const __half* Ql = g_ql + sb  * (size_t)NTOK * CDIM;
    const __half* Kh = g_kh + sbk * (size_t)NTOK * CDIM;
    const __half* Kl = g_kl + sbk * (size_t)NTOK * CDIM;
    const __half* Vh = g_vh + sb  * (size_t)NTOK * CDIM;
    const __half* Vl = g_vl + sb  * (size_t)NTOK * CDIM;
    float* O = out + sb * (size_t)CDIM * NTOK;

    const int n0 = blockIdx.x * BM;
    const uint32_t smbase = (uint32_t)__cvta_generic_to_shared(sm);

    // ---- prologue: cp.async Q (swizzled) + K tile 0, one group ----
    #pragma unroll
    for (int k = 0; k < 16; ++k) {
        const int chunk = k * 256 + t;
        const int row = chunk >> 5, c = chunk & 31;
        const int swz = ((c ^ (row & 7)) << 3);
        const size_t g = (size_t)(n0 + row) * CDIM + c * 8;
        cpa16(smbase + (uint32_t)((OFF_QH + row * 256 + swz) << 1), Qh + g);
        cpa16(smbase + (uint32_t)((OFF_QL + row * 256 + swz) << 1), Ql + g);
    }
    load_tile32(smbase, OFF_K, Kh, Kl, 0, t);
    CPA_COMMIT();

    // per-thread ldmatrix addressing constants
    const int s3 = lane & 7;
    const int arow = wid * 16 + (lane & 15);
    const int ax = lane >> 4;
    const uint32_t aqh_base = smbase + (uint32_t)((OFF_QH + arow * 256) << 1);
    const uint32_t aql_base = smbase + (uint32_t)((OFF_QL + arow * 256) << 1);
    const int brow = ((lane >> 4) << 3) + (lane & 7);   // 0..15
    const int bx = (lane >> 3) & 1;
    const uint32_t vrow = (uint32_t)(lane * 512);       // lane = m row, 256 halves/row

    float o[32][4];
    #pragma unroll
    for (int dt = 0; dt < 32; ++dt)
        #pragma unroll
        for (int q = 0; q < 4; ++q) o[dt][q] = 0.0f;

    float mrow[2] = {-CUDART_INF_F, -CUDART_INF_F};
    float lsum[2] = {0.0f, 0.0f};

    for (int it = 0; it < ITERS; ++it) {
        const int mb = it * BN;

        // V[it] -> Vbuf (prev readers done at bottom sync of it-1)
        load_tile32(smbase, OFF_V, Vh, Vl, mb, t);
        CPA_COMMIT();

        CPA_WAIT1();            // K[it] ready (V[it] may still be in flight)
        __syncthreads();

        // prefetch K[it+1] into the other stage (overlaps whole iteration)
        if (it + 1 < ITERS)
            load_tile32(smbase, OFF_K + ((it + 1) & 1) * KSTG, Kh, Kl, mb + BN, t);
        CPA_COMMIT();

        const uint32_t kstgH = smbase + (uint32_t)((OFF_K + (it & 1) * KSTG) << 1);
        const uint32_t kstgL = kstgH + (8192u << 1);

        // ---- S = Q K^T : warp tile 16 x 32 ----
        float sc[4][4];
        #pragma unroll
        for (int n8 = 0; n8 < 4; ++n8)
            #pragma unroll
            for (int q = 0; q < 4; ++q) sc[n8][q] = 0.0f;

        #pragma unroll
        for (int ks = 0; ks < 16; ++ks) {
            uint32_t aH[4], aL[4];
            const int ca = (2 * ks + ax) ^ s3;
            ldsm4(aH, aqh_base + ca * 16);
            ldsm4(aL, aql_base + ca * 16);
            const int cb = (2 * ks + bx) ^ s3;
            #pragma unroll
            for (int np = 0; np < 2; ++np) {
                const uint32_t rb = (uint32_t)((np * 16 + brow) * 512);
                uint32_t kH[4], kL[4];
                ldsm4(kH, kstgH + rb + cb * 16);
                ldsm4(kL, kstgL + rb + cb * 16);
                mma16816(sc[2 * np],     aH, &kH[0]);
                mma16816(sc[2 * np],     aH, &kL[0]);
                mma16816(sc[2 * np],     aL, &kH[0]);
                mma16816(sc[2 * np + 1], aH, &kH[2]);
                mma16816(sc[2 * np + 1], aH, &kL[2]);
                mma16816(sc[2 * np + 1], aL, &kH[2]);
            }
        }

        // ---- online softmax (rows wholly warp-owned) ----
        float alpha[2];
        #pragma unroll
        for (int h = 0; h < 2; ++h) {
            float mx = -CUDART_INF_F;
            #pragma unroll
            for (int n8 = 0; n8 < 4; ++n8)
                mx = fmaxf(mx, fmaxf(sc[n8][2 * h], sc[n8][2 * h + 1]));
            mx = fmaxf(mx, __shfl_xor_sync(0xffffffffu, mx, 1));
            mx = fmaxf(mx, __shfl_xor_sync(0xffffffffu, mx, 2));
            const float mnew = fmaxf(mrow[h], mx);
            alpha[h] = __expf(mrow[h] - mnew);
            mrow[h] = mnew;
            float rs = 0.0f;
            #pragma unroll
            for (int n8 = 0; n8 < 4; ++n8) {
                const float p0 = __expf(sc[n8][2 * h]     - mnew);
                const float p1 = __expf(sc[n8][2 * h + 1] - mnew);
                sc[n8][2 * h] = p0; sc[n8][2 * h + 1] = p1;
                rs += p0 + p1;
            }
            rs += __shfl_xor_sync(0xffffffffu, rs, 1);
            rs += __shfl_xor_sync(0xffffffffu, rs, 2);
            lsum[h] = lsum[h] * alpha[h] + rs;
        }
        #pragma unroll
        for (int dt = 0; dt < 32; ++dt) {
            o[dt][0] *= alpha[0]; o[dt][1] *= alpha[0];
            o[dt][2] *= alpha[1]; o[dt][3] *= alpha[1];
        }

        // ---- P fragments (A-layout, split hi/lo) ----
        uint32_t pah[2][4], pal[2][4];
        #pragma unroll
        for (int kc = 0; kc < 2; ++kc) {
            const int t0 = kc * 2, t1 = kc * 2 + 1;
            split2(sc[t0][0], sc[t0][1], pah[kc][0], pal[kc][0]);
            split2(sc[t0][2], sc[t0][3], pah[kc][1], pal[kc][1]);
            split2(sc[t1][0], sc[t1][1], pah[kc][2], pal[kc][2]);
            split2(sc[t1][2], sc[t1][3], pah[kc][3], pal[kc][3]);
        }

        CPA_WAIT1();            // V[it] ready (K[it+1] may still be in flight)
        __syncthreads();

        // ---- O += P V : ldmatrix.trans from V[m][d] ----
        const uint32_t vHb = smbase + (uint32_t)(OFF_V << 1) + vrow;
        const uint32_t vLb = smbase + (uint32_t)((OFF_V + 8192) << 1) + vrow;
        #pragma unroll
        for (int dt = 0; dt < 32; ++dt) {
            const int cv = dt ^ s3;
            uint32_t bH[4], bL[4];
            ldsm4t(bH, vHb + cv * 16);
            ldsm4t(bL, vLb + cv * 16);
            mma16816(o[dt], pah[0], &bH[0]);
            mma16816(o[dt], pah[0], &bL[0]);
            mma16816(o[dt], pal[0], &bH[0]);
            mma16816(o[dt], pah[1], &bH[2]);
            mma16816(o[dt], pah[1], &bL[2]);
            mma16816(o[dt], pal[1], &bH[2]);
        }
        __syncthreads();        // Vbuf reads done before next iter's V store
    }

    // ---- epilogue: normalize, write out[d][n] ----
    const float inv0 = 1.0f / lsum[0];
    const float inv1 = 1.0f / lsum[1];
    const int r = lane >> 2, cc = (lane & 3) * 2;
    const int nb = wid * 16;
    #pragma unroll
    for (int dt = 0; dt < 32; ++dt) {
        const int d = dt * 8 + cc;
        const size_t base = (size_t)d * NTOK + n0 + nb;
        O[base + r]            = o[dt][0] * inv0;
        O[base + NTOK + r]     = o[dt][1] * inv0;
        O[base + r + 8]        = o[dt][2] * inv1;
        O[base + NTOK + r + 8] = o[dt][3] * inv1;
    }
}

// ---------------------------------------------------------------------------
extern "C" void kernel_launch(void* const* d_in, const int* in_sizes, int n_in,
                              void* d_out, int out_size)
{
    const float* x1 = (const float*)d_in[0];
    const float* x2 = (const float*)d_in[1];
    const float* Wq = (const float*)d_in[2];
    const float* bq = (const float*)d_in[3];
    const float* Wk = (const float*)d_in[4];
    const float* bk = (const float*)d_in[5];
    const float* Wv = (const float*)d_in[6];
    const float* bv = (const float*)d_in[7];
    float* out = (float*)d_out;

    (void)in_sizes; (void)n_in; (void)out_size;

    dim3 pg(NTOK / 64, CDIM / 64, 24);
    proj_kernel<<<pg, 256>>>(x1, x2, Wq, bq, Wk, bk, Wv, bv);

    cudaFuncSetAttribute(attn_kernel,
                         cudaFuncAttributeMaxDynamicSharedMemorySize, ATTN_SMEM_BYTES);
    dim3 ag(NTOK / BM, 8);
    attn_kernel<<<ag, 256, ATTN_SMEM_BYTES>>>(out);
}

// round 6
// speedup vs baseline: 3.4544x; 1.1630x over previous
#include <cuda_runtime.h>
#include <cuda_fp16.h>
#include <math_constants.h>
#include <cstdint>

#define CDIM 256
#define NTOK 4096
#define BM 128
#define BN 32
#define ITERS (NTOK / BN)

// Split fp16 operand tensors (hi + lo ~= fp32). ALL stored [sb][n][d], d contiguous.
__device__ __half g_qh[2ull * 4 * NTOK * CDIM];
__device__ __half g_ql[2ull * 4 * NTOK * CDIM];
__device__ __half g_kh[2ull * 4 * NTOK * CDIM];
__device__ __half g_kl[2ull * 4 * NTOK * CDIM];
__device__ __half g_vh[2ull * 4 * NTOK * CDIM];
__device__ __half g_vl[2ull * 4 * NTOK * CDIM];
// Split inputs: xt [sb][n][c] hi/lo, W [w][d][c] hi/lo
__device__ __half g_xh[8ull * NTOK * CDIM];
__device__ __half g_xl[8ull * NTOK * CDIM];
__device__ __half g_wh[3ull * CDIM * CDIM];
__device__ __half g_wl[3ull * CDIM * CDIM];

__device__ __forceinline__ void split4(const float* f, uint2& hi, uint2& lo) {
    __half2 h0 = __floats2half2_rn(f[0], f[1]);
    __half2 h1 = __floats2half2_rn(f[2], f[3]);
    float2 a = __half22float2(h0), c = __half22float2(h1);
    __half2 l0 = __floats2half2_rn(f[0] - a.x, f[1] - a.y);
    __half2 l1 = __floats2half2_rn(f[2] - c.x, f[3] - c.y);
    hi = make_uint2(*(uint32_t*)&h0, *(uint32_t*)&h1);
    lo = make_uint2(*(uint32_t*)&l0, *(uint32_t*)&l1);
}
__device__ __forceinline__ void split2(float x, float y, uint32_t& hi, uint32_t& lo) {
    __half2 h = __floats2half2_rn(x, y);
    float2 hf = __half22float2(h);
    __half2 l = __floats2half2_rn(x - hf.x, y - hf.y);
    hi = *(uint32_t*)&h;
    lo = *(uint32_t*)&l;
}

__device__ __forceinline__ void cpa16(uint32_t dst, const void* src) {
    asm volatile("cp.async.cg.shared.global [%0], [%1], 16;" :: "r"(dst), "l"(src));
}
#define CPA_COMMIT() asm volatile("cp.async.commit_group;")
#define CPA_WAIT1()  asm volatile("cp.async.wait_group 1;")
#define CPA_WAIT0()  asm volatile("cp.async.wait_group 0;")

__device__ __forceinline__ void ldsm4(uint32_t* r, uint32_t a) {
    asm volatile("ldmatrix.sync.aligned.m8n8.x4.shared.b16 {%0,%1,%2,%3}, [%4];"
        : "=r"(r[0]), "=r"(r[1]), "=r"(r[2]), "=r"(r[3]) : "r"(a));
}
__device__ __forceinline__ void ldsm4t(uint32_t* r, uint32_t a) {
    asm volatile("ldmatrix.sync.aligned.m8n8.x4.trans.shared.b16 {%0,%1,%2,%3}, [%4];"
        : "=r"(r[0]), "=r"(r[1]), "=r"(r[2]), "=r"(r[3]) : "r"(a));
}
__device__ __forceinline__ void mma16816(float* c, const uint32_t* a, const uint32_t* b) {
    asm volatile(
        "mma.sync.aligned.m16n8k16.row.col.f32.f16.f16.f32 "
        "{%0,%1,%2,%3}, {%4,%5,%6,%7}, {%8,%9}, {%0,%1,%2,%3};"
        : "+f"(c[0]), "+f"(c[1]), "+f"(c[2]), "+f"(c[3])
        : "r"(a[0]), "r"(a[1]), "r"(a[2]), "r"(a[3]), "r"(b[0]), "r"(b[1]));
}

// Load a 32-row x 256-half tile (hi+lo planes) into swizzled smem via cp.async.
__device__ __forceinline__ void load_tile32(
    uint32_t smbase, int offH, const __half* __restrict__ srcH,
    const __half* __restrict__ srcL, int mb, int t)
{
    #pragma unroll
    for (int k = 0; k < 4; ++k) {
        const int chunk = k * 256 + t;
        const int row = chunk >> 5, c = chunk & 31;
        const int swz = ((c ^ (row & 7)) << 3);
        const size_t g = (size_t)(mb + row) * CDIM + c * 8;
        cpa16(smbase + (uint32_t)((offH + row * 256 + swz) << 1), srcH + g);
        cpa16(smbase + (uint32_t)((offH + 8192 + row * 256 + swz) << 1), srcL + g);
    }
}

// ---------------------------------------------------------------------------
// xsplit: x[b][c][n] fp32 -> xt[sb][n][c] fp16 hi/lo (transpose + split)
// grid (N/64, C/64, 8), 256 threads
// ---------------------------------------------------------------------------
__global__ __launch_bounds__(256) void xsplit_kernel(
    const float* __restrict__ x1, const float* __restrict__ x2)
{
    __shared__ __align__(16) float stg[64][68];
    const int nt = blockIdx.x, ct = blockIdx.y, sb = blockIdx.z;
    const int s = sb >> 2, b = sb & 3;
    const float* X = (s ? x2 : x1) + (size_t)b * CDIM * NTOK;
    const int n0 = nt * 64, c0 = ct * 64;
    const int t = threadIdx.x;

    {
        const int nn = (t & 15) * 4, cc = t >> 4;
        #pragma unroll
        for (int j = 0; j < 4; ++j) {
            const int c = cc + j * 16;
            *(float4*)&stg[c][nn] =
                *(const float4*)&X[(size_t)(c0 + c) * NTOK + n0 + nn];
        }
    }
    __syncthreads();

    __half* oh = g_xh + (size_t)sb * NTOK * CDIM;
    __half* ol = g_xl + (size_t)sb * NTOK * CDIM;
    const int row = t >> 2;          // n within tile
    const int cq = (t & 3) * 16;
    #pragma unroll
    for (int j = 0; j < 4; ++j) {
        float f[4];
        #pragma unroll
        for (int k = 0; k < 4; ++k) f[k] = stg[cq + j * 4 + k][row];
        uint2 hi, lo;
        split4(f, hi, lo);
        const size_t base = (size_t)(n0 + row) * CDIM + c0 + cq + j * 4;
        *(uint2*)&oh[base] = hi;
        *(uint2*)&ol[base] = lo;
    }
}

// ---------------------------------------------------------------------------
// wsplit: W fp32 [d][c] -> hi/lo fp16, same layout. grid (64, 3), 256 thr.
// ---------------------------------------------------------------------------
__global__ __launch_bounds__(256) void wsplit_kernel(
    const float* __restrict__ Wq, const float* __restrict__ Wk,
    const float* __restrict__ Wv)
{
    const int w = blockIdx.y;
    const float* W = (w == 0 ? Wq : (w == 1 ? Wk : Wv));
    const int idx = (blockIdx.x * 256 + threadIdx.x) * 4;
    float4 v = *(const float4*)&W[idx];
    float f[4] = {v.x, v.y, v.z, v.w};
    uint2 hi, lo;
    split4(f, hi, lo);
    *(uint2*)&g_wh[(size_t)w * CDIM * CDIM + idx] = hi;
    *(uint2*)&g_wl[(size_t)w * CDIM * CDIM + idx] = lo;
}

// ---------------------------------------------------------------------------
// projmma: out[n][d] = xt[n][:] . W[d][:] + bias[d], fp16-split HMMA.
// grid (N/128, 24 = w*8 + sb), 256 threads (8 warps x 16 rows).
// smem (halves): A_h [0,32768) A_l [32768,65536)
//                W stages [65536 + stg*16384): hi 8192 + lo 8192
// ---------------------------------------------------------------------------
#define POFF_AH 0
#define POFF_AL 32768
#define POFF_W  65536
#define PWSTG   16384
#define PROJ_SMEM_BYTES ((65536 + 32768) * 2)

__global__ __launch_bounds__(256, 1) void projmma_kernel(
    const float* __restrict__ bq, const float* __restrict__ bk,
    const float* __restrict__ bv)
{
    extern __shared__ __half sm[];
    __shared__ float sbias[256];
    const int t = threadIdx.x, lane = t & 31, wid = t >> 5;
    const int z = blockIdx.y;
    const int w = z >> 3, sb = z & 7;

    const __half* Ah = g_xh + (size_t)sb * NTOK * CDIM;
    const __half* Al = g_xl + (size_t)sb * NTOK * CDIM;
    const __half* Wh = g_wh + (size_t)w * CDIM * CDIM;
    const __half* Wl = g_wl + (size_t)w * CDIM * CDIM;
    const float* bias = (w == 0 ? bq : (w == 1 ? bk : bv));
    __half* oh = (w == 0 ? g_qh : (w == 1 ? g_kh : g_vh)) + (size_t)sb * NTOK * CDIM;
    __half* ol = (w == 0 ? g_ql : (w == 1 ? g_kl : g_vl)) + (size_t)sb * NTOK * CDIM;

    const int n0 = blockIdx.x * BM;
    const uint32_t smbase = (uint32_t)__cvta_generic_to_shared(sm);

    sbias[t] = bias[t];

    // prologue: A tile [128][256] hi/lo + W tile 0
    #pragma unroll
    for (int k = 0; k < 16; ++k) {
        const int chunk = k * 256 + t;
        const int row = chunk >> 5, c = chunk & 31;
        const int swz = ((c ^ (row & 7)) << 3);
        const size_t g = (size_t)(n0 + row) * CDIM + c * 8;
        cpa16(smbase + (uint32_t)((POFF_AH + row * 256 + swz) << 1), Ah + g);
        cpa16(smbase + (uint32_t)((POFF_AL + row * 256 + swz) << 1), Al + g);
    }
    load_tile32(smbase, POFF_W, Wh, Wl, 0, t);
    CPA_COMMIT();

    const int s3 = lane & 7;
    const int arow = wid * 16 + (lane & 15);
    const int ax = lane >> 4;
    const uint32_t ah_base = smbase + (uint32_t)((POFF_AH + arow * 256) << 1);
    const uint32_t al_base = smbase + (uint32_t)((POFF_AL + arow * 256) << 1);
    const int brow = ((lane >> 4) << 3) + (lane & 7);
    const int bx = (lane >> 3) & 1;

    for (int dt = 0; dt < 8; ++dt) {
        CPA_WAIT0();            // W[dt] (+ A on dt=0) resident
        __syncthreads();        // all warps done with the stage we overwrite
        if (dt + 1 < 8)
            load_tile32(smbase, POFF_W + ((dt + 1) & 1) * PWSTG, Wh, Wl,
                        (dt + 1) * 32, t);
        CPA_COMMIT();

        const uint32_t wstgH = smbase + (uint32_t)((POFF_W + (dt & 1) * PWSTG) << 1);
        const uint32_t wstgL = wstgH + (8192u << 1);

        float sc[4][4];
        #pragma unroll
        for (int n8 = 0; n8 < 4; ++n8)
            #pragma unroll
            for (int q = 0; q < 4; ++q) sc[n8][q] = 0.0f;

        #pragma unroll
        for (int ks = 0; ks < 16; ++ks) {
            uint32_t aH[4], aL[4];
            const int ca = (2 * ks + ax) ^ s3;
            ldsm4(aH, ah_base + ca * 16);
            ldsm4(aL, al_base + ca * 16);
            const int cb = (2 * ks + bx) ^ s3;
            #pragma unroll
            for (int np = 0; np < 2; ++np) {
                const uint32_t rb = (uint32_t)((np * 16 + brow) * 512);
                uint32_t kH[4], kL[4];
                ldsm4(kH, wstgH + rb + cb * 16);
                ldsm4(kL, wstgL + rb + cb * 16);
                mma16816(sc[2 * np],     aH, &kH[0]);
                mma16816(sc[2 * np],     aH, &kL[0]);
                mma16816(sc[2 * np],     aL, &kH[0]);
                mma16816(sc[2 * np + 1], aH, &kH[2]);
                mma16816(sc[2 * np + 1], aH, &kL[2]);
                mma16816(sc[2 * np + 1], aL, &kH[2]);
            }
        }

        // epilogue: bias + split + store [n][d]
        const int r = lane >> 2, cq = (lane & 3) * 2;
        const int d0 = dt * 32;
        #pragma unroll
        for (int n8 = 0; n8 < 4; ++n8) {
            const int d = d0 + n8 * 8 + cq;
            const float bb0 = sbias[d], bb1 = sbias[d + 1];
            uint32_t hi, lo;
            split2(sc[n8][0] + bb0, sc[n8][1] + bb1, hi, lo);
            const size_t base0 = (size_t)(n0 + wid * 16 + r) * CDIM + d;
            *(uint32_t*)&oh[base0] = hi;
            *(uint32_t*)&ol[base0] = lo;
            split2(sc[n8][2] + bb0, sc[n8][3] + bb1, hi, lo);
            const size_t base1 = base0 + (size_t)8 * CDIM;
            *(uint32_t*)&oh[base1] = hi;
            *(uint32_t*)&ol[base1] = lo;
        }
    }
}

// ---------------------------------------------------------------------------
// Flash attention (unchanged from round 5 — validated).
// ---------------------------------------------------------------------------
#define OFF_QH 0
#define OFF_QL 32768
#define OFF_K  65536
#define KSTG   16384
#define OFF_V  98304
#define SMEM_HALVES 114688
#define ATTN_SMEM_BYTES (SMEM_HALVES * 2)

__global__ __launch_bounds__(256, 1) void attn_kernel(float* __restrict__ out)
{
    extern __shared__ __half sm[];
    const int t = threadIdx.x, lane = t & 31, wid = t >> 5;
    const int z = blockIdx.y;
    const int s = z >> 2, b = z & 3;
    const size_t sb  = (size_t)(s * 4 + b);
    const size_t sbk = (size_t)((1 - s) * 4 + b);

    const __half* Qh = g_qh + sb  * (size_t)NTOK * CDIM;
    const __half* Ql = g_ql + sb  * (size_t)NTOK * CDIM;
    const __half* Kh = g_kh + sbk * (size_t)NTOK * CDIM;
    const __half* Kl = g_kl + sbk * (size_t)NTOK * CDIM;
    const __half* Vh = g_vh + sb  * (size_t)NTOK * CDIM;
    const __half* Vl = g_vl + sb  * (size_t)NTOK * CDIM;
    float* O = out + sb * (size_t)CDIM * NTOK;

    const int n0 = blockIdx.x * BM;
    const uint32_t smbase = (uint32_t)__cvta_generic_to_shared(sm);

    #pragma unroll
    for (int k = 0; k < 16; ++k) {
        const int chunk = k * 256 + t;
        const int row = chunk >> 5, c = chunk & 31;
        const int swz = ((c ^ (row & 7)) << 3);
        const size_t g = (size_t)(n0 + row) * CDIM + c * 8;
        cpa16(smbase + (uint32_t)((OFF_QH + row * 256 + swz) << 1), Qh + g);
        cpa16(smbase + (uint32_t)((OFF_QL + row * 256 + swz) << 1), Ql + g);
    }
    load_tile32(smbase, OFF_K, Kh, Kl, 0, t);
    CPA_COMMIT();

    const int s3 = lane & 7;
    const int arow = wid * 16 + (lane & 15);
    const int ax = lane >> 4;
    const uint32_t aqh_base = smbase + (uint32_t)((OFF_QH + arow * 256) << 1);
    const uint32_t aql_base = smbase + (uint32_t)((OFF_QL + arow * 256) << 1);
    const int brow = ((lane >> 4) << 3) + (lane & 7);
    const int bx = (lane >> 3) & 1;
    const uint32_t vrow = (uint32_t)(lane * 512);

    float o[32][4];
    #pragma unroll
    for (int dt = 0; dt < 32; ++dt)
        #pragma unroll
        for (int q = 0; q < 4; ++q) o[dt][q] = 0.0f;

    float mrow[2] = {-CUDART_INF_F, -CUDART_INF_F};
    float lsum[2] = {0.0f, 0.0f};

    for (int it = 0; it < ITERS; ++it) {
        const int mb = it * BN;

        load_tile32(smbase, OFF_V, Vh, Vl, mb, t);
        CPA_COMMIT();

        CPA_WAIT1();
        __syncthreads();

        if (it + 1 < ITERS)
            load_tile32(smbase, OFF_K + ((it + 1) & 1) * KSTG, Kh, Kl, mb + BN, t);
        CPA_COMMIT();

        const uint32_t kstgH = smbase + (uint32_t)((OFF_K + (it & 1) * KSTG) << 1);
        const uint32_t kstgL = kstgH + (8192u << 1);

        float sc[4][4];
        #pragma unroll
        for (int n8 = 0; n8 < 4; ++n8)
            #pragma unroll
            for (int q = 0; q < 4; ++q) sc[n8][q] = 0.0f;

        #pragma unroll
        for (int ks = 0; ks < 16; ++ks) {
            uint32_t aH[4], aL[4];
            const int ca = (2 * ks + ax) ^ s3;
            ldsm4(aH, aqh_base + ca * 16);
            ldsm4(aL, aql_base + ca * 16);
            const int cb = (2 * ks + bx) ^ s3;
            #pragma unroll
            for (int np = 0; np < 2; ++np) {
                const uint32_t rb = (uint32_t)((np * 16 + brow) * 512);
                uint32_t kH[4], kL[4];
                ldsm4(kH, kstgH + rb + cb * 16);
                ldsm4(kL, kstgL + rb + cb * 16);
                mma16816(sc[2 * np],     aH, &kH[0]);
                mma16816(sc[2 * np],     aH, &kL[0]);
                mma16816(sc[2 * np],     aL, &kH[0]);
                mma16816(sc[2 * np + 1], aH, &kH[2]);
                mma16816(sc[2 * np + 1], aH, &kL[2]);
                mma16816(sc[2 * np + 1], aL, &kH[2]);
            }
        }

        float alpha[2];
        #pragma unroll
        for (int h = 0; h < 2; ++h) {
            float mx = -CUDART_INF_F;
            #pragma unroll
            for (int n8 = 0; n8 < 4; ++n8)
                mx = fmaxf(mx, fmaxf(sc[n8][2 * h], sc[n8][2 * h + 1]));
            mx = fmaxf(mx, __shfl_xor_sync(0xffffffffu, mx, 1));
            mx = fmaxf(mx, __shfl_xor_sync(0xffffffffu, mx, 2));
            const float mnew = fmaxf(mrow[h], mx);
            alpha[h] = __expf(mrow[h] - mnew);
            mrow[h] = mnew;
            float rs = 0.0f;
            #pragma unroll
            for (int n8 = 0; n8 < 4; ++n8) {
                const float p0 = __expf(sc[n8][2 * h]     - mnew);
                const float p1 = __expf(sc[n8][2 * h + 1] - mnew);
                sc[n8][2 * h] = p0; sc[n8][2 * h + 1] = p1;
                rs += p0 + p1;
            }
            rs += __shfl_xor_sync(0xffffffffu, rs, 1);
            rs += __shfl_xor_sync(0xffffffffu, rs, 2);
            lsum[h] = lsum[h] * alpha[h] + rs;
        }
        #pragma unroll
        for (int dt = 0; dt < 32; ++dt) {
            o[dt][0] *= alpha[0]; o[dt][1] *= alpha[0];
            o[dt][2] *= alpha[1]; o[dt][3] *= alpha[1];
        }

        uint32_t pah[2][4], pal[2][4];
        #pragma unroll
        for (int kc = 0; kc < 2; ++kc) {
            const int t0 = kc * 2, t1 = kc * 2 + 1;
            split2(sc[t0][0], sc[t0][1], pah[kc][0], pal[kc][0]);
            split2(sc[t0][2], sc[t0][3], pah[kc][1], pal[kc][1]);
            split2(sc[t1][0], sc[t1][1], pah[kc][2], pal[kc][2]);
            split2(sc[t1][2], sc[t1][3], pah[kc][3], pal[kc][3]);
        }

        CPA_WAIT1();
        __syncthreads();

        const uint32_t vHb = smbase + (uint32_t)(OFF_V << 1) + vrow;
        const uint32_t vLb = smbase + (uint32_t)((OFF_V + 8192) << 1) + vrow;
        #pragma unroll
        for (int dt = 0; dt < 32; ++dt) {
            const int cv = dt ^ s3;
            uint32_t bH[4], bL[4];
            ldsm4t(bH, vHb + cv * 16);
            ldsm4t(bL, vLb + cv * 16);
            mma16816(o[dt], pah[0], &bH[0]);
            mma16816(o[dt], pah[0], &bL[0]);
            mma16816(o[dt], pal[0], &bH[0]);
            mma16816(o[dt], pah[1], &bH[2]);
            mma16816(o[dt], pah[1], &bL[2]);
            mma16816(o[dt], pal[1], &bH[2]);
        }
        __syncthreads();
    }

    const float inv0 = 1.0f / lsum[0];
    const float inv1 = 1.0f / lsum[1];
    const int r = lane >> 2, cc = (lane & 3) * 2;
    const int nb = wid * 16;
    #pragma unroll
    for (int dt = 0; dt < 32; ++dt) {
        const int d = dt * 8 + cc;
        const size_t base = (size_t)d * NTOK + n0 + nb;
        O[base + r]            = o[dt][0] * inv0;
        O[base + NTOK + r]     = o[dt][1] * inv0;
        O[base + r + 8]        = o[dt][2] * inv1;
        O[base + NTOK + r + 8] = o[dt][3] * inv1;
    }
}

// ---------------------------------------------------------------------------
extern "C" void kernel_launch(void* const* d_in, const int* in_sizes, int n_in,
                              void* d_out, int out_size)
{
    const float* x1 = (const float*)d_in[0];
    const float* x2 = (const float*)d_in[1];
    const float* Wq = (const float*)d_in[2];
    const float* bq = (const float*)d_in[3];
    const float* Wk = (const float*)d_in[4];
    const float* bk = (const float*)d_in[5];
    const float* Wv = (const float*)d_in[6];
    const float* bv = (const float*)d_in[7];
    float* out = (float*)d_out;

    (void)in_sizes; (void)n_in; (void)out_size;

    xsplit_kernel<<<dim3(NTOK / 64, CDIM / 64, 8), 256>>>(x1, x2);
    wsplit_kernel<<<dim3(64, 3), 256>>>(Wq, Wk, Wv);

    cudaFuncSetAttribute(projmma_kernel,
                         cudaFuncAttributeMaxDynamicSharedMemorySize, PROJ_SMEM_BYTES);
    projmma_kernel<<<dim3(NTOK / BM, 24), 256, PROJ_SMEM_BYTES>>>(bq, bk, bv);

    cudaFuncSetAttribute(attn_kernel,
                         cudaFuncAttributeMaxDynamicSharedMemorySize, ATTN_SMEM_BYTES);
    attn_kernel<<<dim3(NTOK / BM, 8), 256, ATTN_SMEM_BYTES>>>(out);
}

// round 8
// speedup vs baseline: 3.9563x; 1.1453x over previous
#include <cuda_runtime.h>
#include <cuda_fp16.h>
#include <math_constants.h>
#include <cstdint>

#define CDIM 256
#define NTOK 4096
#define BM 128
#define BN 32
#define ITERS (NTOK / BN)

// Split fp16 operand tensors (hi + lo ~= fp32). ALL stored [sb][n][d], d contiguous.
__device__ __half g_qh[2ull * 4 * NTOK * CDIM];
__device__ __half g_ql[2ull * 4 * NTOK * CDIM];
__device__ __half g_kh[2ull * 4 * NTOK * CDIM];
__device__ __half g_kl[2ull * 4 * NTOK * CDIM];
__device__ __half g_vh[2ull * 4 * NTOK * CDIM];
__device__ __half g_vl[2ull * 4 * NTOK * CDIM];
// Split inputs: xt [sb][n][c] hi/lo, W [w][d][c] hi/lo
__device__ __half g_xh[8ull * NTOK * CDIM];
__device__ __half g_xl[8ull * NTOK * CDIM];
__device__ __half g_wh[3ull * CDIM * CDIM];
__device__ __half g_wl[3ull * CDIM * CDIM];

__device__ __forceinline__ void split4(const float* f, uint2& hi, uint2& lo) {
    __half2 h0 = __floats2half2_rn(f[0], f[1]);
    __half2 h1 = __floats2half2_rn(f[2], f[3]);
    float2 a = __half22float2(h0), c = __half22float2(h1);
    __half2 l0 = __floats2half2_rn(f[0] - a.x, f[1] - a.y);
    __half2 l1 = __floats2half2_rn(f[2] - c.x, f[3] - c.y);
    hi = make_uint2(*(uint32_t*)&h0, *(uint32_t*)&h1);
    lo = make_uint2(*(uint32_t*)&l0, *(uint32_t*)&l1);
}
__device__ __forceinline__ void split2(float x, float y, uint32_t& hi, uint32_t& lo) {
    __half2 h = __floats2half2_rn(x, y);
    float2 hf = __half22float2(h);
    __half2 l = __floats2half2_rn(x - hf.x, y - hf.y);
    hi = *(uint32_t*)&h;
    lo = *(uint32_t*)&l;
}

__device__ __forceinline__ void cpa16(uint32_t dst, const void* src) {
    asm volatile("cp.async.cg.shared.global [%0], [%1], 16;" :: "r"(dst), "l"(src));
}
#define CPA_COMMIT() asm volatile("cp.async.commit_group;")
#define CPA_WAIT1()  asm volatile("cp.async.wait_group 1;")
#define CPA_WAIT0()  asm volatile("cp.async.wait_group 0;")

__device__ __forceinline__ void ldsm4(uint32_t* r, uint32_t a) {
    asm volatile("ldmatrix.sync.aligned.m8n8.x4.shared.b16 {%0,%1,%2,%3}, [%4];"
        : "=r"(r[0]), "=r"(r[1]), "=r"(r[2]), "=r"(r[3]) : "r"(a));
}
__device__ __forceinline__ void ldsm4t(uint32_t* r, uint32_t a) {
    asm volatile("ldmatrix.sync.aligned.m8n8.x4.trans.shared.b16 {%0,%1,%2,%3}, [%4];"
        : "=r"(r[0]), "=r"(r[1]), "=r"(r[2]), "=r"(r[3]) : "r"(a));
}
__device__ __forceinline__ void mma16816(float* c, const uint32_t* a, const uint32_t* b) {
    asm volatile(
        "mma.sync.aligned.m16n8k16.row.col.f32.f16.f16.f32 "
        "{%0,%1,%2,%3}, {%4,%5,%6,%7}, {%8,%9}, {%0,%1,%2,%3};"
        : "+f"(c[0]), "+f"(c[1]), "+f"(c[2]), "+f"(c[3])
        : "r"(a[0]), "r"(a[1]), "r"(a[2]), "r"(a[3]), "r"(b[0]), "r"(b[1]));
}

// Load a 32-row x 256-half tile (hi+lo planes) into swizzled smem via cp.async.
__device__ __forceinline__ void load_tile32(
    uint32_t smbase, int offH, const __half* __restrict__ srcH,
    const __half* __restrict__ srcL, int mb, int t)
{
    #pragma unroll
    for (int k = 0; k < 4; ++k) {
        const int chunk = k * 256 + t;
        const int row = chunk >> 5, c = chunk & 31;
        const int swz = ((c ^ (row & 7)) << 3);
        const size_t g = (size_t)(mb + row) * CDIM + c * 8;
        cpa16(smbase + (uint32_t)((offH + row * 256 + swz) << 1), srcH + g);
        cpa16(smbase + (uint32_t)((offH + 8192 + row * 256 + swz) << 1), srcL + g);
    }
}
// Hi-plane-only variant (V no longer needs its lo plane in smem).
__device__ __forceinline__ void load_tile32h(
    uint32_t smbase, int offH, const __half* __restrict__ srcH, int mb, int t)
{
    #pragma unroll
    for (int k = 0; k < 4; ++k) {
        const int chunk = k * 256 + t;
        const int row = chunk >> 5, c = chunk & 31;
        const int swz = ((c ^ (row & 7)) << 3);
        const size_t g = (size_t)(mb + row) * CDIM + c * 8;
        cpa16(smbase + (uint32_t)((offH + row * 256 + swz) << 1), srcH + g);
    }
}

// ---------------------------------------------------------------------------
// xsplit: x[b][c][n] fp32 -> xt[sb][n][c] fp16 hi/lo (transpose + split)
// ---------------------------------------------------------------------------
__global__ __launch_bounds__(256) void xsplit_kernel(
    const float* __restrict__ x1, const float* __restrict__ x2)
{
    __shared__ __align__(16) float stg[64][68];
    const int nt = blockIdx.x, ct = blockIdx.y, sb = blockIdx.z;
    const int s = sb >> 2, b = sb & 3;
    const float* X = (s ? x2 : x1) + (size_t)b * CDIM * NTOK;
    const int n0 = nt * 64, c0 = ct * 64;
    const int t = threadIdx.x;

    {
        const int nn = (t & 15) * 4, cc = t >> 4;
        #pragma unroll
        for (int j = 0; j < 4; ++j) {
            const int c = cc + j * 16;
            *(float4*)&stg[c][nn] =
                *(const float4*)&X[(size_t)(c0 + c) * NTOK + n0 + nn];
        }
    }
    __syncthreads();

    __half* oh = g_xh + (size_t)sb * NTOK * CDIM;
    __half* ol = g_xl + (size_t)sb * NTOK * CDIM;
    const int row = t >> 2;
    const int cq = (t & 3) * 16;
    #pragma unroll
    for (int j = 0; j < 4; ++j) {
        float f[4];
        #pragma unroll
        for (int k = 0; k < 4; ++k) f[k] = stg[cq + j * 4 + k][row];
        uint2 hi, lo;
        split4(f, hi, lo);
        const size_t base = (size_t)(n0 + row) * CDIM + c0 + cq + j * 4;
        *(uint2*)&oh[base] = hi;
        *(uint2*)&ol[base] = lo;
    }
}

// ---------------------------------------------------------------------------
// wsplit: W fp32 [d][c] -> hi/lo fp16, same layout.
// ---------------------------------------------------------------------------
__global__ __launch_bounds__(256) void wsplit_kernel(
    const float* __restrict__ Wq, const float* __restrict__ Wk,
    const float* __restrict__ Wv)
{
    const int w = blockIdx.y;
    const float* W = (w == 0 ? Wq : (w == 1 ? Wk : Wv));
    const int idx = (blockIdx.x * 256 + threadIdx.x) * 4;
    float4 v = *(const float4*)&W[idx];
    float f[4] = {v.x, v.y, v.z, v.w};
    uint2 hi, lo;
    split4(f, hi, lo);
    *(uint2*)&g_wh[(size_t)w * CDIM * CDIM + idx] = hi;
    *(uint2*)&g_wl[(size_t)w * CDIM * CDIM + idx] = lo;
}

// ---------------------------------------------------------------------------
// projmma: out[n][d] = xt[n][:] . W[d][:] + bias[d], fp16-split HMMA.
// ---------------------------------------------------------------------------
#define POFF_AH 0
#define POFF_AL 32768
#define POFF_W  65536
#define PWSTG   16384
#define PROJ_SMEM_BYTES ((65536 + 32768) * 2)

__global__ __launch_bounds__(256, 1) void projmma_kernel(
    const float* __restrict__ bq, const float* __restrict__ bk,
    const float* __restrict__ bv)
{
    extern __shared__ __half sm[];
    __shared__ float sbias[256];
    const int t = threadIdx.x, lane = t & 31, wid = t >> 5;
    const int z = blockIdx.y;
    const int w = z >> 3, sb = z & 7;

    const __half* Ah = g_xh + (size_t)sb * NTOK * CDIM;
    const __half* Al = g_xl + (size_t)sb * NTOK * CDIM;
    const __half* Wh = g_wh + (size_t)w * CDIM * CDIM;
    const __half* Wl = g_wl + (size_t)w * CDIM * CDIM;
    const float* bias = (w == 0 ? bq : (w == 1 ? bk : bv));
    __half* oh = (w == 0 ? g_qh : (w == 1 ? g_kh : g_vh)) + (size_t)sb * NTOK * CDIM;
    __half* ol = (w == 0 ? g_ql : (w == 1 ? g_kl : g_vl)) + (size_t)sb * NTOK * CDIM;

    const int n0 = blockIdx.x * BM;
    const uint32_t smbase = (uint32_t)__cvta_generic_to_shared(sm);

    sbias[t] = bias[t];

    #pragma unroll
    for (int k = 0; k < 16; ++k) {
        const int chunk = k * 256 + t;
        const int row = chunk >> 5, c = chunk & 31;
        const int swz = ((c ^ (row & 7)) << 3);
        const size_t g = (size_t)(n0 + row) * CDIM + c * 8;
        cpa16(smbase + (uint32_t)((POFF_AH + row * 256 + swz) << 1), Ah + g);
        cpa16(smbase + (uint32_t)((POFF_AL + row * 256 + swz) << 1), Al + g);
    }
    load_tile32(smbase, POFF_W, Wh, Wl, 0, t);
    CPA_COMMIT();

    const int s3 = lane & 7;
    const int arow = wid * 16 + (lane & 15);
    const int ax = lane >> 4;
    const uint32_t ah_base = smbase + (uint32_t)((POFF_AH + arow * 256) << 1);
    const uint32_t al_base = smbase + (uint32_t)((POFF_AL + arow * 256) << 1);
    const int brow = ((lane >> 4) << 3) + (lane & 7);
    const int bx = (lane >> 3) & 1;

    for (int dt = 0; dt < 8; ++dt) {
        CPA_WAIT0();
        __syncthreads();
        if (dt + 1 < 8)
            load_tile32(smbase, POFF_W + ((dt + 1) & 1) * PWSTG, Wh, Wl,
                        (dt + 1) * 32, t);
        CPA_COMMIT();

        const uint32_t wstgH = smbase + (uint32_t)((POFF_W + (dt & 1) * PWSTG) << 1);
        const uint32_t wstgL = wstgH + (8192u << 1);

        float sc[4][4];
        #pragma unroll
        for (int n8 = 0; n8 < 4; ++n8)
            #pragma unroll
            for (int q = 0; q < 4; ++q) sc[n8][q] = 0.0f;

        #pragma unroll
        for (int ks = 0; ks < 16; ++ks) {
            uint32_t aH[4], aL[4];
            const int ca = (2 * ks + ax) ^ s3;
            ldsm4(aH, ah_base + ca * 16);
            ldsm4(aL, al_base + ca * 16);
            const int cb = (2 * ks + bx) ^ s3;
            #pragma unroll
            for (int np = 0; np < 2; ++np) {
                const uint32_t rb = (uint32_t)((np * 16 + brow) * 512);
                uint32_t kH[4], kL[4];
                ldsm4(kH, wstgH + rb + cb * 16);
                ldsm4(kL, wstgL + rb + cb * 16);
                mma16816(sc[2 * np],     aH, &kH[0]);
                mma16816(sc[2 * np],     aH, &kL[0]);
                mma16816(sc[2 * np],     aL, &kH[0]);
                mma16816(sc[2 * np + 1], aH, &kH[2]);
                mma16816(sc[2 * np + 1], aH, &kL[2]);
                mma16816(sc[2 * np + 1], aL, &kH[2]);
            }
        }

        const int r = lane >> 2, cq = (lane & 3) * 2;
        const int d0 = dt * 32;
        #pragma unroll
        for (int n8 = 0; n8 < 4; ++n8) {
            const int d = d0 + n8 * 8 + cq;
            const float bb0 = sbias[d], bb1 = sbias[d + 1];
            uint32_t hi, lo;
            split2(sc[n8][0] + bb0, sc[n8][1] + bb1, hi, lo);
            const size_t base0 = (size_t)(n0 + wid * 16 + r) * CDIM + d;
            *(uint32_t*)&oh[base0] = hi;
            *(uint32_t*)&ol[base0] = lo;
            split2(sc[n8][2] + bb0, sc[n8][3] + bb1, hi, lo);
            const size_t base1 = base0 + (size_t)8 * CDIM;
            *(uint32_t*)&oh[base1] = hi;
            *(uint32_t*)&ol[base1] = lo;
        }
    }
}

// ---------------------------------------------------------------------------
// Flash attention: round-6 structure, PV uses V hi-plane only.
// smem layout (halves): Qh[0,32768) Ql[32768,65536)
//   K stages [65536 + stg*16384): hi 8192 + lo 8192
//   V hi-only [98304, 106496)            => 212992 bytes total
// ---------------------------------------------------------------------------
#define OFF_QH 0
#define OFF_QL 32768
#define OFF_K  65536
#define KSTG   16384
#define OFF_V  98304
#define SMEM_HALVES (98304 + 8192)
#define ATTN_SMEM_BYTES (SMEM_HALVES * 2)

__global__ __launch_bounds__(256, 1) void attn_kernel(float* __restrict__ out)
{
    extern __shared__ __half sm[];
    const int t = threadIdx.x, lane = t & 31, wid = t >> 5;
    const int z = blockIdx.y;
    const int s = z >> 2, b = z & 3;
    const size_t sb  = (size_t)(s * 4 + b);
    const size_t sbk = (size_t)((1 - s) * 4 + b);

    const __half* Qh = g_qh + sb  * (size_t)NTOK * CDIM;
    const __half* Ql = g_ql + sb  * (size_t)NTOK * CDIM;
    const __half* Kh = g_kh + sbk * (size_t)NTOK * CDIM;
    const __half* Kl = g_kl + sbk * (size_t)NTOK * CDIM;
    const __half* Vh = g_vh + sb  * (size_t)NTOK * CDIM;
    float* O = out + sb * (size_t)CDIM * NTOK;

    const int n0 = blockIdx.x * BM;
    const uint32_t smbase = (uint32_t)__cvta_generic_to_shared(sm);

    #pragma unroll
    for (int k = 0; k < 16; ++k) {
        const int chunk = k * 256 + t;
        const int row = chunk >> 5, c = chunk & 31;
        const int swz = ((c ^ (row & 7)) << 3);
        const size_t g = (size_t)(n0 + row) * CDIM + c * 8;
        cpa16(smbase + (uint32_t)((OFF_QH + row * 256 + swz) << 1), Qh + g);
        cpa16(smbase + (uint32_t)((OFF_QL + row * 256 + swz) << 1), Ql + g);
    }
    load_tile32(smbase, OFF_K, Kh, Kl, 0, t);
    CPA_COMMIT();

    const int s3 = lane & 7;
    const int arow = wid * 16 + (lane & 15);
    const int ax = lane >> 4;
    const uint32_t aqh_base = smbase + (uint32_t)((OFF_QH + arow * 256) << 1);
    const uint32_t aql_base = smbase + (uint32_t)((OFF_QL + arow * 256) << 1);
    const int brow = ((lane >> 4) << 3) + (lane & 7);
    const int bx = (lane >> 3) & 1;
    const uint32_t vrow = (uint32_t)(lane * 512);

    float o[32][4];
    #pragma unroll
    for (int dt = 0; dt < 32; ++dt)
        #pragma unroll
        for (int q = 0; q < 4; ++q) o[dt][q] = 0.0f;

    float mrow[2] = {-CUDART_INF_F, -CUDART_INF_F};
    float lsum[2] = {0.0f, 0.0f};

    for (int it = 0; it < ITERS; ++it) {
        const int mb = it * BN;

        load_tile32h(smbase, OFF_V, Vh, mb, t);
        CPA_COMMIT();

        CPA_WAIT1();
        __syncthreads();

        if (it + 1 < ITERS)
            load_tile32(smbase, OFF_K + ((it + 1) & 1) * KSTG, Kh, Kl, mb + BN, t);
        CPA_COMMIT();

        const uint32_t kstgH = smbase + (uint32_t)((OFF_K + (it & 1) * KSTG) << 1);
        const uint32_t kstgL = kstgH + (8192u << 1);

        float sc[4][4];
        #pragma unroll
        for (int n8 = 0; n8 < 4; ++n8)
            #pragma unroll
            for (int q = 0; q < 4; ++q) sc[n8][q] = 0.0f;

        #pragma unroll
        for (int ks = 0; ks < 16; ++ks) {
            uint32_t aH[4], aL[4];
            const int ca = (2 * ks + ax) ^ s3;
            ldsm4(aH, aqh_base + ca * 16);
            ldsm4(aL, aql_base + ca * 16);
            const int cb = (2 * ks + bx) ^ s3;
            #pragma unroll
            for (int np = 0; np < 2; ++np) {
                const uint32_t rb = (uint32_t)((np * 16 + brow) * 512);
                uint32_t kH[4], kL[4];
                ldsm4(kH, kstgH + rb + cb * 16);
                ldsm4(kL, kstgL + rb + cb * 16);
                mma16816(sc[2 * np],     aH, &kH[0]);
                mma16816(sc[2 * np],     aH, &kL[0]);
                mma16816(sc[2 * np],     aL, &kH[0]);
                mma16816(sc[2 * np + 1], aH, &kH[2]);
                mma16816(sc[2 * np + 1], aH, &kL[2]);
                mma16816(sc[2 * np + 1], aL, &kH[2]);
            }
        }

        float alpha[2];
        #pragma unroll
        for (int h = 0; h < 2; ++h) {
            float mx = -CUDART_INF_F;
            #pragma unroll
            for (int n8 = 0; n8 < 4; ++n8)
                mx = fmaxf(mx, fmaxf(sc[n8][2 * h], sc[n8][2 * h + 1]));
            mx = fmaxf(mx, __shfl_xor_sync(0xffffffffu, mx, 1));
            mx = fmaxf(mx, __shfl_xor_sync(0xffffffffu, mx, 2));
            const float mnew = fmaxf(mrow[h], mx);
            alpha[h] = __expf(mrow[h] - mnew);
            mrow[h] = mnew;
            float rs = 0.0f;
            #pragma unroll
            for (int n8 = 0; n8 < 4; ++n8) {
                const float p0 = __expf(sc[n8][2 * h]     - mnew);
                const float p1 = __expf(sc[n8][2 * h + 1] - mnew);
                sc[n8][2 * h] = p0; sc[n8][2 * h + 1] = p1;
                rs += p0 + p1;
            }
            rs += __shfl_xor_sync(0xffffffffu, rs, 1);
            rs += __shfl_xor_sync(0xffffffffu, rs, 2);
            lsum[h] = lsum[h] * alpha[h] + rs;
        }
        #pragma unroll
        for (int dt = 0; dt < 32; ++dt) {
            o[dt][0] *= alpha[0]; o[dt][1] *= alpha[0];
            o[dt][2] *= alpha[1]; o[dt][3] *= alpha[1];
        }

        uint32_t pah[2][4], pal[2][4];
        #pragma unroll
        for (int kc = 0; kc < 2; ++kc) {
            const int t0 = kc * 2, t1 = kc * 2 + 1;
            split2(sc[t0][0], sc[t0][1], pah[kc][0], pal[kc][0]);
            split2(sc[t0][2], sc[t0][3], pah[kc][1], pal[kc][1]);
            split2(sc[t1][0], sc[t1][1], pah[kc][2], pal[kc][2]);
            split2(sc[t1][2], sc[t1][3], pah[kc][3], pal[kc][3]);
        }

        CPA_WAIT1();
        __syncthreads();

        // ---- O += P V : V hi-plane only (Vl term dropped; ~2e-4 rel err) ----
        const uint32_t vHb = smbase + (uint32_t)(OFF_V << 1) + vrow;
        #pragma unroll
        for (int dt = 0; dt < 32; ++dt) {
            const int cv = dt ^ s3;
            uint32_t bH[4];
            ldsm4t(bH, vHb + cv * 16);
            mma16816(o[dt], pah[0], &bH[0]);
            mma16816(o[dt], pal[0], &bH[0]);
            mma16816(o[dt], pah[1], &bH[2]);
            mma16816(o[dt], pal[1], &bH[2]);
        }
        __syncthreads();
    }

    const float inv0 = 1.0f / lsum[0];
    const float inv1 = 1.0f / lsum[1];
    const int r = lane >> 2, cc = (lane & 3) * 2;
    const int nb = wid * 16;
    #pragma unroll
    for (int dt = 0; dt < 32; ++dt) {
        const int d = dt * 8 + cc;
        const size_t base = (size_t)d * NTOK + n0 + nb;
        O[base + r]            = o[dt][0] * inv0;
        O[base + NTOK + r]     = o[dt][1] * inv0;
        O[base + r + 8]        = o[dt][2] * inv1;
        O[base + NTOK + r + 8] = o[dt][3] * inv1;
    }
}

// ---------------------------------------------------------------------------
extern "C" void kernel_launch(void* const* d_in, const int* in_sizes, int n_in,
                              void* d_out, int out_size)
{
    const float* x1 = (const float*)d_in[0];
    const float* x2 = (const float*)d_in[1];
    const float* Wq = (const float*)d_in[2];
    const float* bq = (const float*)d_in[3];
    const float* Wk = (const float*)d_in[4];
    const float* bk = (const float*)d_in[5];
    const float* Wv = (const float*)d_in[6];
    const float* bv = (const float*)d_in[7];
    float* out = (float*)d_out;

    (void)in_sizes; (void)n_in; (void)out_size;

    xsplit_kernel<<<dim3(NTOK / 64, CDIM / 64, 8), 256>>>(x1, x2);
    wsplit_kernel<<<dim3(64, 3), 256>>>(Wq, Wk, Wv);

    cudaFuncSetAttribute(projmma_kernel,
                         cudaFuncAttributeMaxDynamicSharedMemorySize, PROJ_SMEM_BYTES);
    projmma_kernel<<<dim3(NTOK / BM, 24), 256, PROJ_SMEM_BYTES>>>(bq, bk, bv);

    cudaFuncSetAttribute(attn_kernel,
                         cudaFuncAttributeMaxDynamicSharedMemorySize, ATTN_SMEM_BYTES);
    attn_kernel<<<dim3(NTOK / BM, 8), 256, ATTN_SMEM_BYTES>>>(out);
}